// round 2
// baseline (speedup 1.0000x reference)
#include <cuda_runtime.h>
#include <math.h>

// ---------------- problem constants ----------------
#define NN   16384
#define DD   512
#define BSb  16
#define MMc  256
#define DCc  512
#define HH   8
#define DHh  64
#define LL   4
#define EE   262144
#define NKV  (BSb*MMc)      /* 4096 rows of cond */
#define EPSf 1e-5f

// ---------------- scratch (device globals; no allocation allowed) ----------------
__device__ float g_h [NN*DD];
__device__ float g_ln[NN*DD];
__device__ float g_q [NN*DD];
__device__ float g_o [NN*DD];
__device__ float g_k [NKV*DD];
__device__ float g_v [NKV*DD];
__device__ float g_f [NN*2048];     // GEGLU val / output (134 MB)
__device__ float g_sum[DD], g_sq[DD], g_mu[DD], g_rstd[DD];
__device__ float g_deg[NN], g_dinv[NN];
__device__ float g_nrm[EE];
__device__ int   g_src[EE], g_dst[EE];
__device__ int   g_is64;

// ---------------- edge index dtype detect + convert ----------------
__global__ void k_detect(const int* e) {
    if (threadIdx.x == 0 && blockIdx.x == 0) {
        int nz = 0;
        for (int j = 0; j < 64; j++) nz += (e[2*j + 1] != 0);
        g_is64 = (nz == 0) ? 1 : 0;   // int64 little-endian: every high word is 0
    }
}
__global__ void k_convert(const void* eptr) {
    int i = blockIdx.x * 256 + threadIdx.x;
    if (i >= EE) return;
    if (g_is64) {
        const long long* p = (const long long*)eptr;
        g_src[i] = (int)p[i];  g_dst[i] = (int)p[EE + i];
    } else {
        const int* p = (const int*)eptr;
        g_src[i] = p[i];       g_dst[i] = p[EE + i];
    }
}
__global__ void k_deg_init() { int i = blockIdx.x*256 + threadIdx.x; if (i < NN) g_deg[i] = 1.0f; }
__global__ void k_deg_edges(){ int i = blockIdx.x*256 + threadIdx.x; if (i < EE) atomicAdd(&g_deg[g_dst[i]], 1.0f); }
__global__ void k_dinv()     { int i = blockIdx.x*256 + threadIdx.x; if (i < NN) g_dinv[i] = rsqrtf(g_deg[i]); }
__global__ void k_norm()     { int i = blockIdx.x*256 + threadIdx.x; if (i < EE) g_nrm[i] = g_dinv[g_src[i]] * g_dinv[g_dst[i]]; }

// ---------------- generic zero ----------------
__global__ void k_zero(float4* p, int n4) {
    for (int i = blockIdx.x*blockDim.x + threadIdx.x; i < n4; i += gridDim.x*blockDim.x)
        p[i] = make_float4(0.f, 0.f, 0.f, 0.f);
}

// ---------------- BatchNorm (training-mode batch stats) ----------------
__global__ void k_bnstat_zero() { int c = threadIdx.x; g_sum[c] = 0.f; g_sq[c] = 0.f; }
__global__ void k_bn_partial(const float* __restrict__ x) {
    int c = threadIdx.x;                 // 512 threads = 512 columns
    int r0 = blockIdx.x * 256;           // 64 blocks * 256 rows
    float s = 0.f, q = 0.f;
    for (int r = 0; r < 256; r++) {
        float v = x[(size_t)(r0 + r)*DD + c];
        s += v; q += v*v;
    }
    atomicAdd(&g_sum[c], s); atomicAdd(&g_sq[c], q);
}
__global__ void k_bn_final() {
    int c = threadIdx.x;
    float mu = g_sum[c] * (1.0f/NN);
    g_mu[c] = mu;
    g_rstd[c] = rsqrtf(g_sq[c]*(1.0f/NN) - mu*mu + EPSf);
}
__global__ void k_bn_apply(const float* __restrict__ x, const float* __restrict__ w, const float* __restrict__ b) {
    int idx = blockIdx.x*256 + threadIdx.x;         // over NN*DD/4
    if (idx >= NN*DD/4) return;
    int c = (idx & 127) * 4;
    float4 xv = ((const float4*)x)[idx];
    float4 o;
    o.x = (xv.x - g_mu[c+0]) * g_rstd[c+0] * w[c+0] + b[c+0];
    o.y = (xv.y - g_mu[c+1]) * g_rstd[c+1] * w[c+1] + b[c+1];
    o.z = (xv.z - g_mu[c+2]) * g_rstd[c+2] * w[c+2] + b[c+2];
    o.w = (xv.w - g_mu[c+3]) * g_rstd[c+3] * w[c+3] + b[c+3];
    ((float4*)g_ln)[idx] = o;
}

// ---------------- LayerNorm (one warp per row of 512) ----------------
__global__ void k_ln(const float* __restrict__ in, float* __restrict__ out,
                     const float* __restrict__ w, const float* __restrict__ b) {
    int warp = threadIdx.x >> 5, lane = threadIdx.x & 31;
    int row = blockIdx.x * 8 + warp;
    const float4* xr = (const float4*)(in + (size_t)row * DD);
    float4 v[4]; float s = 0.f, q = 0.f;
#pragma unroll
    for (int j = 0; j < 4; j++) {
        v[j] = xr[j*32 + lane];
        s += v[j].x + v[j].y + v[j].z + v[j].w;
        q += v[j].x*v[j].x + v[j].y*v[j].y + v[j].z*v[j].z + v[j].w*v[j].w;
    }
#pragma unroll
    for (int o = 16; o > 0; o >>= 1) {
        s += __shfl_xor_sync(0xffffffffu, s, o);
        q += __shfl_xor_sync(0xffffffffu, q, o);
    }
    float mu = s * (1.0f/DD);
    float rs = rsqrtf(q*(1.0f/DD) - mu*mu + EPSf);
    float4* orow = (float4*)(out + (size_t)row * DD);
    const float4* w4 = (const float4*)w; const float4* b4 = (const float4*)b;
#pragma unroll
    for (int j = 0; j < 4; j++) {
        int c = j*32 + lane;
        float4 wv = w4[c], bv = b4[c], r;
        r.x = (v[j].x - mu)*rs*wv.x + bv.x;
        r.y = (v[j].y - mu)*rs*wv.y + bv.y;
        r.z = (v[j].z - mu)*rs*wv.z + bv.z;
        r.w = (v[j].w - mu)*rs*wv.w + bv.w;
        orow[c] = r;
    }
}

// ---------------- SGEMM: C = A[MxK] @ B[K x *] (+bias) (+res / gelu-epilogue) ----------------
// mode 0: C = A@B (+bias) (+res)
// mode 1: gate pass of GEGLU: g = A@B + bias; C = C_prev * gelu(g)
__global__ __launch_bounds__(256) void k_gemm(
    const float* __restrict__ A, const float* __restrict__ B, float* __restrict__ C,
    const float* __restrict__ bias, const float* __restrict__ res,
    int M, int K, int ldb, int ldc, int mode)
{
    __shared__ float As[16][128];
    __shared__ float Bs[16][128];
    int tid = threadIdx.x;
    int brow = blockIdx.y, bcol = blockIdx.x;
    A += (size_t)brow * 128 * K;
    B += bcol * 128;
    size_t coff = (size_t)brow * 128 * ldc + (size_t)bcol * 128;

    int arow = tid >> 2, acol = (tid & 3) << 2;     // A: 64 rows/pass, 4 cols/thread
    int brw  = tid >> 5, bcl  = (tid & 31) << 2;    // B: 8 rows/pass

    float acc[8][8];
#pragma unroll
    for (int i = 0; i < 8; i++)
#pragma unroll
        for (int j = 0; j < 8; j++) acc[i][j] = 0.f;

    int ty = tid >> 4, tx = tid & 15;

    for (int k0 = 0; k0 < K; k0 += 16) {
        float4 a0 = *(const float4*)(A + (size_t)arow      * K + k0 + acol);
        float4 a1 = *(const float4*)(A + (size_t)(arow+64) * K + k0 + acol);
        As[acol+0][arow] = a0.x; As[acol+1][arow] = a0.y;
        As[acol+2][arow] = a0.z; As[acol+3][arow] = a0.w;
        As[acol+0][arow+64] = a1.x; As[acol+1][arow+64] = a1.y;
        As[acol+2][arow+64] = a1.z; As[acol+3][arow+64] = a1.w;
        float4 b0 = *(const float4*)(B + (size_t)(k0 + brw    ) * ldb + bcl);
        float4 b1 = *(const float4*)(B + (size_t)(k0 + brw + 8) * ldb + bcl);
        *(float4*)&Bs[brw    ][bcl] = b0;
        *(float4*)&Bs[brw + 8][bcl] = b1;
        __syncthreads();
#pragma unroll
        for (int k = 0; k < 16; k++) {
            float4 m0 = *(float4*)&As[k][ty*8];
            float4 m1 = *(float4*)&As[k][ty*8 + 4];
            float4 n0 = *(float4*)&Bs[k][tx*8];
            float4 n1 = *(float4*)&Bs[k][tx*8 + 4];
            float rm[8] = {m0.x,m0.y,m0.z,m0.w,m1.x,m1.y,m1.z,m1.w};
            float rn[8] = {n0.x,n0.y,n0.z,n0.w,n1.x,n1.y,n1.z,n1.w};
#pragma unroll
            for (int i = 0; i < 8; i++)
#pragma unroll
                for (int j = 0; j < 8; j++) acc[i][j] += rm[i]*rn[j];
        }
        __syncthreads();
    }

#pragma unroll
    for (int i = 0; i < 8; i++) {
        size_t rowoff = coff + (size_t)(ty*8 + i) * ldc + tx*8;
#pragma unroll
        for (int jb = 0; jb < 2; jb++) {
            float4 v = make_float4(acc[i][jb*4+0], acc[i][jb*4+1], acc[i][jb*4+2], acc[i][jb*4+3]);
            if (bias) {
                int gc = bcol*128 + tx*8 + jb*4;
                v.x += bias[gc+0]; v.y += bias[gc+1]; v.z += bias[gc+2]; v.w += bias[gc+3];
            }
            if (mode == 1) {
                // v is the gate; multiply previously-stored val by gelu(gate)
                float4 valv = *(const float4*)(C + rowoff + jb*4);
                v.x = valv.x * (0.5f*v.x*(1.0f + erff(v.x*0.70710678118654752f)));
                v.y = valv.y * (0.5f*v.y*(1.0f + erff(v.y*0.70710678118654752f)));
                v.z = valv.z * (0.5f*v.z*(1.0f + erff(v.z*0.70710678118654752f)));
                v.w = valv.w * (0.5f*v.w*(1.0f + erff(v.w*0.70710678118654752f)));
            } else if (res) {
                float4 rv = *(const float4*)(res + rowoff + jb*4);
                v.x += rv.x; v.y += rv.y; v.z += rv.z; v.w += rv.w;
            }
            *(float4*)(C + rowoff + jb*4) = v;
        }
    }
}

// ---------------- GCN scatter: out[dst] += g[src]*norm (coalesced per edge) ----------------
__global__ void k_scatter(const float* __restrict__ g, float* __restrict__ out) {
    int idx = blockIdx.x*256 + threadIdx.x;   // EE*128 threads, 4 floats each
    if (idx >= EE*128) return;
    int e = idx >> 7;
    int c = (idx & 127) << 2;
    int s = g_src[e], d = g_dst[e];
    float nm = g_nrm[e];
    float4 gv = *(const float4*)(g + (size_t)s*DD + c);
    float* op = out + (size_t)d*DD + c;
    atomicAdd(op+0, gv.x*nm); atomicAdd(op+1, gv.y*nm);
    atomicAdd(op+2, gv.z*nm); atomicAdd(op+3, gv.w*nm);
}
__global__ void k_selfbias(const float* __restrict__ g, float* __restrict__ h, const float* __restrict__ b) {
    int idx = blockIdx.x*256 + threadIdx.x;
    if (idx >= NN*DD/4) return;
    int row = idx >> 7; int c = (idx & 127) * 4;
    float di = g_dinv[row]; float sn = di*di;
    float4 gv = ((const float4*)g)[idx];
    float4 hv = ((float4*)h)[idx];
    hv.x += gv.x*sn + b[c+0]; hv.y += gv.y*sn + b[c+1];
    hv.z += gv.z*sn + b[c+2]; hv.w += gv.w*sn + b[c+3];
    ((float4*)h)[idx] = hv;
}
__global__ void k_final(const float* __restrict__ scat, const float* __restrict__ g,
                        const float* __restrict__ b, const float* __restrict__ x,
                        float* __restrict__ out) {
    int idx = blockIdx.x*256 + threadIdx.x;
    if (idx >= NN*DD/4) return;
    int row = idx >> 7; int c = (idx & 127) * 4;
    float di = g_dinv[row]; float sn = di*di;
    float4 sv = ((const float4*)scat)[idx];
    float4 gv = ((const float4*)g)[idx];
    float4 xv = ((const float4*)x)[idx];
    float4 o;
    o.x = sv.x + gv.x*sn + b[c+0] + xv.x;
    o.y = sv.y + gv.y*sn + b[c+1] + xv.y;
    o.z = sv.z + gv.z*sn + b[c+2] + xv.z;
    o.w = sv.w + gv.w*sn + b[c+3] + xv.w;
    ((float4*)out)[idx] = o;
}

// ---------------- fused cross-attention ----------------
// grid (BS*H, 16), block 256. 64 query rows per block; K,V = 256 x 64 per (b,h).
#define AT_SMEM ((64*64 + 256*65 + 256*64 + 64*256)*4)
__global__ __launch_bounds__(256) void k_attn() {
    extern __shared__ float sm[];
    float* Qs = sm;                  // [64][64]
    float* Ks = Qs + 64*64;          // [256][65] (padded)
    float* Vs = Ks + 256*65;         // [256][64]
    float* Ps = Vs + 256*64;         // [64][256]

    int bh = blockIdx.x; int b = bh >> 3; int hh = bh & 7;
    int tile = blockIdx.y;
    int tid = threadIdx.x;

    const float* qg = g_q + ((size_t)(b*1024 + tile*64)) * DD + hh*64;
    const float* kg = g_k + ((size_t)(b*256)) * DD + hh*64;
    const float* vg = g_v + ((size_t)(b*256)) * DD + hh*64;

    for (int t = tid; t < 64*16; t += 256) {
        int r = t >> 4, c4 = (t & 15) * 4;
        *(float4*)&Qs[r*64 + c4] = *(const float4*)(qg + (size_t)r*DD + c4);
    }
    for (int t = tid; t < 256*16; t += 256) {
        int r = t >> 4, c4 = (t & 15) * 4;
        float4 kv = *(const float4*)(kg + (size_t)r*DD + c4);
        Ks[r*65 + c4 + 0] = kv.x; Ks[r*65 + c4 + 1] = kv.y;
        Ks[r*65 + c4 + 2] = kv.z; Ks[r*65 + c4 + 3] = kv.w;
        *(float4*)&Vs[r*64 + c4] = *(const float4*)(vg + (size_t)r*DD + c4);
    }
    __syncthreads();

    int ty = tid >> 4, tx = tid & 15;
    float acc[4][16];
#pragma unroll
    for (int i = 0; i < 4; i++)
#pragma unroll
        for (int j = 0; j < 16; j++) acc[i][j] = 0.f;

#pragma unroll 4
    for (int k = 0; k < 64; k++) {
        float a[4];
#pragma unroll
        for (int i = 0; i < 4; i++) a[i] = Qs[(ty*4 + i)*64 + k];
#pragma unroll
        for (int j = 0; j < 16; j++) {
            float bb = Ks[(tx + 16*j)*65 + k];
#pragma unroll
            for (int i = 0; i < 4; i++) acc[i][j] += a[i]*bb;
        }
    }

    const float scale = 0.125f;   // DH^-0.5
#pragma unroll
    for (int i = 0; i < 4; i++) {
        float mx = -1e30f;
#pragma unroll
        for (int j = 0; j < 16; j++) { acc[i][j] *= scale; mx = fmaxf(mx, acc[i][j]); }
#pragma unroll
        for (int o = 8; o > 0; o >>= 1) mx = fmaxf(mx, __shfl_xor_sync(0xffffffffu, mx, o));
        float s = 0.f;
#pragma unroll
        for (int j = 0; j < 16; j++) { acc[i][j] = __expf(acc[i][j] - mx); s += acc[i][j]; }
#pragma unroll
        for (int o = 8; o > 0; o >>= 1) s += __shfl_xor_sync(0xffffffffu, s, o);
        float inv = 1.0f / s;
#pragma unroll
        for (int j = 0; j < 16; j++) Ps[(ty*4 + i)*256 + tx + 16*j] = acc[i][j]*inv;
    }
    __syncthreads();

    float o[4][4];
#pragma unroll
    for (int i = 0; i < 4; i++)
#pragma unroll
        for (int j = 0; j < 4; j++) o[i][j] = 0.f;

#pragma unroll 4
    for (int m = 0; m < 256; m++) {
        float a[4];
#pragma unroll
        for (int i = 0; i < 4; i++) a[i] = Ps[(ty*4 + i)*256 + m];
        float4 bv = *(const float4*)&Vs[m*64 + tx*4];
#pragma unroll
        for (int i = 0; i < 4; i++) {
            o[i][0] += a[i]*bv.x; o[i][1] += a[i]*bv.y;
            o[i][2] += a[i]*bv.z; o[i][3] += a[i]*bv.w;
        }
    }
    float* og = g_o + ((size_t)(b*1024 + tile*64)) * DD + hh*64;
#pragma unroll
    for (int i = 0; i < 4; i++)
        *(float4*)(og + (size_t)(ty*4 + i)*DD + tx*4) = make_float4(o[i][0], o[i][1], o[i][2], o[i][3]);
}

// ---------------- host ----------------
static void gemm(const float* A, const float* B, float* C,
                 const float* bias, const float* res,
                 int M, int Nc, int K, int ldb, int ldc, int mode) {
    dim3 grid(Nc/128, M/128);
    k_gemm<<<grid, 256>>>(A, B, C, bias, res, M, K, ldb, ldc, mode);
}

extern "C" void kernel_launch(void* const* d_in, const int* in_sizes, int n_in,
                              void* d_out, int out_size) {
    const float* x        = (const float*)d_in[0];
    const void*  eidx     = d_in[1];
    const float* cond     = (const float*)d_in[2];
    const float* bn_w     = (const float*)d_in[3];
    const float* bn_b     = (const float*)d_in[4];
    const float* gcn_in_w = (const float*)d_in[5];
    const float* gcn_in_b = (const float*)d_in[6];
    const float* gcn_out_w= (const float*)d_in[7];
    const float* gcn_out_b= (const float*)d_in[8];
    const float* Wq       = (const float*)d_in[9];
    const float* Wk       = (const float*)d_in[10];
    const float* Wv       = (const float*)d_in[11];
    const float* Wo       = (const float*)d_in[12];
    const float* ln2_w    = (const float*)d_in[13];
    const float* ln2_b    = (const float*)d_in[14];
    const float* ln3_w    = (const float*)d_in[15];
    const float* ln3_b    = (const float*)d_in[16];
    const float* geglu_w  = (const float*)d_in[17];
    const float* geglu_b  = (const float*)d_in[18];
    const float* ffo_w    = (const float*)d_in[19];
    const float* ffo_b    = (const float*)d_in[20];

    void *hb_, *lnb_, *qb_, *ob_, *kb_, *vb_, *fb_;
    cudaGetSymbolAddress(&hb_,  g_h);  cudaGetSymbolAddress(&lnb_, g_ln);
    cudaGetSymbolAddress(&qb_,  g_q);  cudaGetSymbolAddress(&ob_,  g_o);
    cudaGetSymbolAddress(&kb_,  g_k);  cudaGetSymbolAddress(&vb_,  g_v);
    cudaGetSymbolAddress(&fb_,  g_f);
    float* hb  = (float*)hb_;  float* lnb = (float*)lnb_;
    float* qb  = (float*)qb_;  float* ob  = (float*)ob_;
    float* kb  = (float*)kb_;  float* vb  = (float*)vb_;
    float* fb  = (float*)fb_;

    cudaFuncSetAttribute(k_attn, cudaFuncAttributeMaxDynamicSharedMemorySize, AT_SMEM);

    const int NDv4 = NN*DD/4;

    // edges: detect dtype, convert, degrees, norms
    k_detect  <<<1, 32>>>((const int*)eidx);
    k_convert <<<EE/256, 256>>>(eidx);
    k_deg_init<<<NN/256, 256>>>();
    k_deg_edges<<<EE/256, 256>>>();
    k_dinv    <<<NN/256, 256>>>();
    k_norm    <<<EE/256, 256>>>();

    // BatchNorm -> g_ln
    k_bnstat_zero<<<1, 512>>>();
    k_bn_partial <<<64, 512>>>(x);
    k_bn_final   <<<1, 512>>>();
    k_bn_apply   <<<NDv4/256, 256>>>(x, bn_w, bn_b);

    // GCN in: g_q = bn @ W ; h = scatter + self + bias
    gemm(lnb, gcn_in_w, qb, nullptr, nullptr, NN, DD, DD, DD, DD, 0);
    k_zero    <<<4096, 256>>>((float4*)hb, NDv4);
    k_scatter <<<EE*128/256, 256>>>(qb, hb);
    k_selfbias<<<NDv4/256, 256>>>(qb, hb, gcn_in_b);

    for (int i = 0; i < LL; i++) {
        // attention block
        k_ln<<<NN/8, 256>>>(hb, lnb, ln2_w + i*DD, ln2_b + i*DD);
        gemm(lnb,  Wq + (size_t)i*DD*512,  qb, nullptr, nullptr, NN,  512, DD,  512, 512, 0);
        gemm(cond, Wk + (size_t)i*DCc*512, kb, nullptr, nullptr, NKV, 512, DCc, 512, 512, 0);
        gemm(cond, Wv + (size_t)i*DCc*512, vb, nullptr, nullptr, NKV, 512, DCc, 512, 512, 0);
        k_attn<<<dim3(BSb*HH, 16), 256, AT_SMEM>>>();
        gemm(ob, Wo + (size_t)i*512*DD, hb, nullptr, hb, NN, DD, 512, DD, DD, 0);  // h += o @ Wo
        // feed-forward (GEGLU), two passes, no u buffer
        k_ln<<<NN/8, 256>>>(hb, lnb, ln3_w + i*DD, ln3_b + i*DD);
        // val pass: f = ln @ W[:, :2048] + b[:2048]
        gemm(lnb, geglu_w + (size_t)i*DD*4096, fb,
             geglu_b + (size_t)i*4096, nullptr, NN, 2048, DD, 4096, 2048, 0);
        // gate pass: f = f * gelu(ln @ W[:, 2048:] + b[2048:])
        gemm(lnb, geglu_w + (size_t)i*DD*4096 + 2048, fb,
             geglu_b + (size_t)i*4096 + 2048, nullptr, NN, 2048, DD, 4096, 2048, 1);
        gemm(fb, ffo_w + (size_t)i*2048*DD, hb, ffo_b + (size_t)i*DD, hb, NN, DD, 2048, DD, DD, 0); // h += f@W+b
    }

    // GCN out + residual input
    gemm(hb, gcn_out_w, qb, nullptr, nullptr, NN, DD, DD, DD, DD, 0);
    k_zero   <<<4096, 256>>>((float4*)ob, NDv4);
    k_scatter<<<EE*128/256, 256>>>(qb, ob);
    k_final  <<<NDv4/256, 256>>>(ob, qb, gcn_out_b, x, (float*)d_out);
}

// round 3
// speedup vs baseline: 1.7634x; 1.7634x over previous
#include <cuda_runtime.h>
#include <cuda_bf16.h>
#include <math.h>

// ---------------- problem constants ----------------
#define NN   16384
#define DD   512
#define BSb  16
#define MMc  256
#define DCc  512
#define HH   8
#define DHh  64
#define LL   4
#define EE   262144
#define NKV  (BSb*MMc)      /* 4096 rows of cond */
#define EPSf 1e-5f

// ---------------- scratch (device globals; no allocation allowed) ----------------
__device__ float g_h [NN*DD];
__device__ float g_ln[NN*DD];
__device__ float g_q [NN*DD];
__device__ float g_o [NN*DD];
__device__ float g_k [NKV*DD];
__device__ float g_v [NKV*DD];
__device__ float g_f [NN*2048];     // GEGLU val / output (134 MB)
__device__ float g_sum[DD], g_sq[DD], g_mu[DD], g_rstd[DD];
__device__ float g_deg[NN], g_dinv[NN];
__device__ float g_nrm[EE];
__device__ int   g_src[EE], g_dst[EE];
__device__ int   g_is64;

// ---------------- edge index dtype detect + convert ----------------
__global__ void k_detect(const int* e) {
    if (threadIdx.x == 0 && blockIdx.x == 0) {
        int nz = 0;
        for (int j = 0; j < 64; j++) nz += (e[2*j + 1] != 0);
        g_is64 = (nz == 0) ? 1 : 0;   // int64 little-endian: every high word is 0
    }
}
__global__ void k_convert(const void* eptr) {
    int i = blockIdx.x * 256 + threadIdx.x;
    if (i >= EE) return;
    if (g_is64) {
        const long long* p = (const long long*)eptr;
        g_src[i] = (int)p[i];  g_dst[i] = (int)p[EE + i];
    } else {
        const int* p = (const int*)eptr;
        g_src[i] = p[i];       g_dst[i] = p[EE + i];
    }
}
__global__ void k_deg_init() { int i = blockIdx.x*256 + threadIdx.x; if (i < NN) g_deg[i] = 1.0f; }
__global__ void k_deg_edges(){ int i = blockIdx.x*256 + threadIdx.x; if (i < EE) atomicAdd(&g_deg[g_dst[i]], 1.0f); }
__global__ void k_dinv()     { int i = blockIdx.x*256 + threadIdx.x; if (i < NN) g_dinv[i] = rsqrtf(g_deg[i]); }
__global__ void k_norm()     { int i = blockIdx.x*256 + threadIdx.x; if (i < EE) g_nrm[i] = g_dinv[g_src[i]] * g_dinv[g_dst[i]]; }

// ---------------- generic zero ----------------
__global__ void k_zero(float4* p, int n4) {
    for (int i = blockIdx.x*blockDim.x + threadIdx.x; i < n4; i += gridDim.x*blockDim.x)
        p[i] = make_float4(0.f, 0.f, 0.f, 0.f);
}

// ---------------- BatchNorm (training-mode batch stats) ----------------
__global__ void k_bnstat_zero() { int c = threadIdx.x; g_sum[c] = 0.f; g_sq[c] = 0.f; }
__global__ void k_bn_partial(const float* __restrict__ x) {
    int c = threadIdx.x;
    int r0 = blockIdx.x * 256;
    float s = 0.f, q = 0.f;
    for (int r = 0; r < 256; r++) {
        float v = x[(size_t)(r0 + r)*DD + c];
        s += v; q += v*v;
    }
    atomicAdd(&g_sum[c], s); atomicAdd(&g_sq[c], q);
}
__global__ void k_bn_final() {
    int c = threadIdx.x;
    float mu = g_sum[c] * (1.0f/NN);
    g_mu[c] = mu;
    g_rstd[c] = rsqrtf(g_sq[c]*(1.0f/NN) - mu*mu + EPSf);
}
__global__ void k_bn_apply(const float* __restrict__ x, const float* __restrict__ w, const float* __restrict__ b) {
    int idx = blockIdx.x*256 + threadIdx.x;
    if (idx >= NN*DD/4) return;
    int c = (idx & 127) * 4;
    float4 xv = ((const float4*)x)[idx];
    float4 o;
    o.x = (xv.x - g_mu[c+0]) * g_rstd[c+0] * w[c+0] + b[c+0];
    o.y = (xv.y - g_mu[c+1]) * g_rstd[c+1] * w[c+1] + b[c+1];
    o.z = (xv.z - g_mu[c+2]) * g_rstd[c+2] * w[c+2] + b[c+2];
    o.w = (xv.w - g_mu[c+3]) * g_rstd[c+3] * w[c+3] + b[c+3];
    ((float4*)g_ln)[idx] = o;
}

// ---------------- LayerNorm (one warp per row of 512) ----------------
__global__ void k_ln(const float* __restrict__ in, float* __restrict__ out,
                     const float* __restrict__ w, const float* __restrict__ b) {
    int warp = threadIdx.x >> 5, lane = threadIdx.x & 31;
    int row = blockIdx.x * 8 + warp;
    const float4* xr = (const float4*)(in + (size_t)row * DD);
    float4 v[4]; float s = 0.f, q = 0.f;
#pragma unroll
    for (int j = 0; j < 4; j++) {
        v[j] = xr[j*32 + lane];
        s += v[j].x + v[j].y + v[j].z + v[j].w;
        q += v[j].x*v[j].x + v[j].y*v[j].y + v[j].z*v[j].z + v[j].w*v[j].w;
    }
#pragma unroll
    for (int o = 16; o > 0; o >>= 1) {
        s += __shfl_xor_sync(0xffffffffu, s, o);
        q += __shfl_xor_sync(0xffffffffu, q, o);
    }
    float mu = s * (1.0f/DD);
    float rs = rsqrtf(q*(1.0f/DD) - mu*mu + EPSf);
    float4* orow = (float4*)(out + (size_t)row * DD);
    const float4* w4 = (const float4*)w; const float4* b4 = (const float4*)b;
#pragma unroll
    for (int j = 0; j < 4; j++) {
        int c = j*32 + lane;
        float4 wv = w4[c], bv = b4[c], r;
        r.x = (v[j].x - mu)*rs*wv.x + bv.x;
        r.y = (v[j].y - mu)*rs*wv.y + bv.y;
        r.z = (v[j].z - mu)*rs*wv.z + bv.z;
        r.w = (v[j].w - mu)*rs*wv.w + bv.w;
        orow[c] = r;
    }
}

// ================= tensor-core GEMM (bf16 split, fp32-accurate) =================
// C[M x N] = A[M x K] @ B[K x N], BM=BN=128, BK=32, 256 thr (8 warps, 2x4),
// warp tile 64x32. A smem K-contig (stride 40 halves), B smem N-contig
// (stride 136 halves). x = hi + lo split; acc += Ah*Bh + Ah*Bl + Al*Bh.
#define A_STR 40
#define B_STR 136
#define A_TILE_H (128*A_STR)   /* 5120 halves */
#define B_TILE_H (32*B_STR)    /* 4352 halves */
#define SM_AHI(s) ((s)*A_TILE_H)
#define SM_ALO(s) ((2+(s))*A_TILE_H)
#define SM_BHI(s) (4*A_TILE_H + (s)*B_TILE_H)
#define SM_BLO(s) (4*A_TILE_H + (2+(s))*B_TILE_H)
#define SMEM_GEMM ((4*A_TILE_H + 4*B_TILE_H)*2)   /* 75776 bytes */

__device__ __forceinline__ void ldsm_x4(unsigned addr, unsigned &r0, unsigned &r1, unsigned &r2, unsigned &r3) {
    asm volatile("ldmatrix.sync.aligned.m8n8.x4.shared.b16 {%0,%1,%2,%3}, [%4];"
        : "=r"(r0), "=r"(r1), "=r"(r2), "=r"(r3) : "r"(addr));
}
__device__ __forceinline__ void ldsm_x2t(unsigned addr, unsigned &r0, unsigned &r1) {
    asm volatile("ldmatrix.sync.aligned.m8n8.x2.trans.shared.b16 {%0,%1}, [%2];"
        : "=r"(r0), "=r"(r1) : "r"(addr));
}
__device__ __forceinline__ void mma16816(float* c, unsigned a0, unsigned a1, unsigned a2, unsigned a3,
                                         unsigned b0, unsigned b1) {
    asm volatile("mma.sync.aligned.m16n8k16.row.col.f32.bf16.bf16.f32 "
        "{%0,%1,%2,%3},{%4,%5,%6,%7},{%8,%9},{%0,%1,%2,%3};"
        : "+f"(c[0]), "+f"(c[1]), "+f"(c[2]), "+f"(c[3])
        : "r"(a0), "r"(a1), "r"(a2), "r"(a3), "r"(b0), "r"(b1));
}
__device__ __forceinline__ void split_store(__nv_bfloat16* hi, __nv_bfloat16* lo, float4 v) {
    __nv_bfloat16 h0 = __float2bfloat16_rn(v.x);
    __nv_bfloat16 h1 = __float2bfloat16_rn(v.y);
    __nv_bfloat16 h2 = __float2bfloat16_rn(v.z);
    __nv_bfloat16 h3 = __float2bfloat16_rn(v.w);
    __nv_bfloat16 l0 = __float2bfloat16_rn(v.x - __bfloat162float(h0));
    __nv_bfloat16 l1 = __float2bfloat16_rn(v.y - __bfloat162float(h1));
    __nv_bfloat16 l2 = __float2bfloat16_rn(v.z - __bfloat162float(h2));
    __nv_bfloat16 l3 = __float2bfloat16_rn(v.w - __bfloat162float(h3));
    uint2 uh, ul;
    uh.x = (unsigned)__bfloat16_as_ushort(h0) | ((unsigned)__bfloat16_as_ushort(h1) << 16);
    uh.y = (unsigned)__bfloat16_as_ushort(h2) | ((unsigned)__bfloat16_as_ushort(h3) << 16);
    ul.x = (unsigned)__bfloat16_as_ushort(l0) | ((unsigned)__bfloat16_as_ushort(l1) << 16);
    ul.y = (unsigned)__bfloat16_as_ushort(l2) | ((unsigned)__bfloat16_as_ushort(l3) << 16);
    *(uint2*)hi = uh;
    *(uint2*)lo = ul;
}

// mode 0: C = A@B (+bias) (+res)
// mode 1: gate pass of GEGLU: g = A@B + bias; C = C_prev * gelu(g)
__global__ __launch_bounds__(256) void k_gemm_tc(
    const float* __restrict__ A, const float* __restrict__ B, float* __restrict__ C,
    const float* __restrict__ bias, const float* __restrict__ res,
    int M, int K, int ldb, int ldc, int mode)
{
    extern __shared__ __align__(16) __nv_bfloat16 sh[];
    const unsigned sbase = (unsigned)__cvta_generic_to_shared(sh);
    const int tid = threadIdx.x;
    const int lane = tid & 31, warp = tid >> 5;
    const int wm = warp >> 2;          // 0..1  (64-row warp tile)
    const int wn = warp & 3;           // 0..3  (32-col warp tile)
    const int brow = blockIdx.y, bcol = blockIdx.x;

    const float* Ab = A + (size_t)brow * 128 * K;
    const float* Bb = B + (size_t)bcol * 128;

    const int arow0 = tid >> 3;        // 0..31  (+ p*32)
    const int akc   = tid & 7;         // float4 chunk within 32-k row
    const int bkr0  = tid >> 5;        // 0..7   (+ p*8)
    const int bc4   = lane << 2;       // 0..124

    float4 pa[4], pb[4];

    float acc[4][4][4];
#pragma unroll
    for (int mt = 0; mt < 4; mt++)
#pragma unroll
        for (int nt = 0; nt < 4; nt++)
#pragma unroll
            for (int e = 0; e < 4; e++) acc[mt][nt][e] = 0.f;

    const int KT = K >> 5;

    // prologue: tile 0
#pragma unroll
    for (int p = 0; p < 4; p++)
        pa[p] = *(const float4*)(Ab + (size_t)(p*32 + arow0)*K + akc*4);
#pragma unroll
    for (int p = 0; p < 4; p++)
        pb[p] = *(const float4*)(Bb + (size_t)(p*8 + bkr0)*ldb + bc4);
#pragma unroll
    for (int p = 0; p < 4; p++) {
        int r = p*32 + arow0;
        split_store(sh + SM_AHI(0) + r*A_STR + akc*4, sh + SM_ALO(0) + r*A_STR + akc*4, pa[p]);
    }
#pragma unroll
    for (int p = 0; p < 4; p++) {
        int kr = p*8 + bkr0;
        split_store(sh + SM_BHI(0) + kr*B_STR + bc4, sh + SM_BLO(0) + kr*B_STR + bc4, pb[p]);
    }

    for (int kt = 0; kt < KT; kt++) {
        __syncthreads();
        int cur = kt & 1;
        if (kt + 1 < KT) {
#pragma unroll
            for (int p = 0; p < 4; p++)
                pa[p] = *(const float4*)(Ab + (size_t)(p*32 + arow0)*K + (kt+1)*32 + akc*4);
#pragma unroll
            for (int p = 0; p < 4; p++)
                pb[p] = *(const float4*)(Bb + (size_t)((kt+1)*32 + p*8 + bkr0)*ldb + bc4);
        }
        // compute on smem[cur]: two k16 steps
#pragma unroll
        for (int kh = 0; kh < 2; kh++) {
            unsigned Ah[4][4], Al[4][4], Bh[4][2], Bl[4][2];
            int arow = wm*64 + (lane & 15);
            int acol = kh*16 + (lane >> 4)*8;     // halves
#pragma unroll
            for (int mt = 0; mt < 4; mt++) {
                unsigned off = (unsigned)(((arow + mt*16)*A_STR + acol) * 2);
                ldsm_x4(sbase + SM_AHI(cur)*2 + off, Ah[mt][0], Ah[mt][1], Ah[mt][2], Ah[mt][3]);
                ldsm_x4(sbase + SM_ALO(cur)*2 + off, Al[mt][0], Al[mt][1], Al[mt][2], Al[mt][3]);
            }
            int bkr = kh*16 + (lane & 15);
#pragma unroll
            for (int nt = 0; nt < 4; nt++) {
                unsigned off = (unsigned)((bkr*B_STR + wn*32 + nt*8) * 2);
                ldsm_x2t(sbase + SM_BHI(cur)*2 + off, Bh[nt][0], Bh[nt][1]);
                ldsm_x2t(sbase + SM_BLO(cur)*2 + off, Bl[nt][0], Bl[nt][1]);
            }
#pragma unroll
            for (int mt = 0; mt < 4; mt++)
#pragma unroll
                for (int nt = 0; nt < 4; nt++) {
                    mma16816(acc[mt][nt], Ah[mt][0], Ah[mt][1], Ah[mt][2], Ah[mt][3], Bh[nt][0], Bh[nt][1]);
                    mma16816(acc[mt][nt], Ah[mt][0], Ah[mt][1], Ah[mt][2], Ah[mt][3], Bl[nt][0], Bl[nt][1]);
                    mma16816(acc[mt][nt], Al[mt][0], Al[mt][1], Al[mt][2], Al[mt][3], Bh[nt][0], Bh[nt][1]);
                }
        }
        if (kt + 1 < KT) {
            int nxt = (kt + 1) & 1;
#pragma unroll
            for (int p = 0; p < 4; p++) {
                int r = p*32 + arow0;
                split_store(sh + SM_AHI(nxt) + r*A_STR + akc*4, sh + SM_ALO(nxt) + r*A_STR + akc*4, pa[p]);
            }
#pragma unroll
            for (int p = 0; p < 4; p++) {
                int kr = p*8 + bkr0;
                split_store(sh + SM_BHI(nxt) + kr*B_STR + bc4, sh + SM_BLO(nxt) + kr*B_STR + bc4, pb[p]);
            }
        }
    }

    // epilogue
    const int g = lane >> 2, tg = lane & 3;
#pragma unroll
    for (int mt = 0; mt < 4; mt++) {
#pragma unroll
        for (int nt = 0; nt < 4; nt++) {
            int lcol = wn*32 + nt*8 + tg*2;
            int gcol = bcol*128 + lcol;
            size_t off0 = ((size_t)brow*128 + wm*64 + mt*16 + g) * ldc + gcol;
            size_t off1 = off0 + 8*(size_t)ldc;
            float2 v0 = make_float2(acc[mt][nt][0], acc[mt][nt][1]);
            float2 v1 = make_float2(acc[mt][nt][2], acc[mt][nt][3]);
            if (bias) {
                float2 bv = *(const float2*)(bias + gcol);
                v0.x += bv.x; v0.y += bv.y; v1.x += bv.x; v1.y += bv.y;
            }
            if (mode == 1) {
                float2 a0 = *(const float2*)(C + off0);
                float2 a1 = *(const float2*)(C + off1);
                v0.x = a0.x * (0.5f*v0.x*(1.0f + erff(v0.x*0.70710678118654752f)));
                v0.y = a0.y * (0.5f*v0.y*(1.0f + erff(v0.y*0.70710678118654752f)));
                v1.x = a1.x * (0.5f*v1.x*(1.0f + erff(v1.x*0.70710678118654752f)));
                v1.y = a1.y * (0.5f*v1.y*(1.0f + erff(v1.y*0.70710678118654752f)));
            } else if (res) {
                float2 r0 = *(const float2*)(res + off0);
                float2 r1 = *(const float2*)(res + off1);
                v0.x += r0.x; v0.y += r0.y; v1.x += r1.x; v1.y += r1.y;
            }
            *(float2*)(C + off0) = v0;
            *(float2*)(C + off1) = v1;
        }
    }
}

// ---------------- GCN scatter: out[dst] += g[src]*norm (coalesced per edge) ----------------
__global__ void k_scatter(const float* __restrict__ g, float* __restrict__ out) {
    int idx = blockIdx.x*256 + threadIdx.x;
    if (idx >= EE*128) return;
    int e = idx >> 7;
    int c = (idx & 127) << 2;
    int s = g_src[e], d = g_dst[e];
    float nm = g_nrm[e];
    float4 gv = *(const float4*)(g + (size_t)s*DD + c);
    float* op = out + (size_t)d*DD + c;
    atomicAdd(op+0, gv.x*nm); atomicAdd(op+1, gv.y*nm);
    atomicAdd(op+2, gv.z*nm); atomicAdd(op+3, gv.w*nm);
}
__global__ void k_selfbias(const float* __restrict__ g, float* __restrict__ h, const float* __restrict__ b) {
    int idx = blockIdx.x*256 + threadIdx.x;
    if (idx >= NN*DD/4) return;
    int row = idx >> 7; int c = (idx & 127) * 4;
    float di = g_dinv[row]; float sn = di*di;
    float4 gv = ((const float4*)g)[idx];
    float4 hv = ((float4*)h)[idx];
    hv.x += gv.x*sn + b[c+0]; hv.y += gv.y*sn + b[c+1];
    hv.z += gv.z*sn + b[c+2]; hv.w += gv.w*sn + b[c+3];
    ((float4*)h)[idx] = hv;
}
__global__ void k_final(const float* __restrict__ scat, const float* __restrict__ g,
                        const float* __restrict__ b, const float* __restrict__ x,
                        float* __restrict__ out) {
    int idx = blockIdx.x*256 + threadIdx.x;
    if (idx >= NN*DD/4) return;
    int row = idx >> 7; int c = (idx & 127) * 4;
    float di = g_dinv[row]; float sn = di*di;
    float4 sv = ((const float4*)scat)[idx];
    float4 gv = ((const float4*)g)[idx];
    float4 xv = ((const float4*)x)[idx];
    float4 o;
    o.x = sv.x + gv.x*sn + b[c+0] + xv.x;
    o.y = sv.y + gv.y*sn + b[c+1] + xv.y;
    o.z = sv.z + gv.z*sn + b[c+2] + xv.z;
    o.w = sv.w + gv.w*sn + b[c+3] + xv.w;
    ((float4*)out)[idx] = o;
}

// ---------------- fused cross-attention ----------------
#define AT_SMEM ((64*64 + 256*65 + 256*64 + 64*256)*4)
__global__ __launch_bounds__(256) void k_attn() {
    extern __shared__ float sm[];
    float* Qs = sm;                  // [64][64]
    float* Ks = Qs + 64*64;          // [256][65]
    float* Vs = Ks + 256*65;         // [256][64]
    float* Ps = Vs + 256*64;         // [64][256]

    int bh = blockIdx.x; int b = bh >> 3; int hh = bh & 7;
    int tile = blockIdx.y;
    int tid = threadIdx.x;

    const float* qg = g_q + ((size_t)(b*1024 + tile*64)) * DD + hh*64;
    const float* kg = g_k + ((size_t)(b*256)) * DD + hh*64;
    const float* vg = g_v + ((size_t)(b*256)) * DD + hh*64;

    for (int t = tid; t < 64*16; t += 256) {
        int r = t >> 4, c4 = (t & 15) * 4;
        *(float4*)&Qs[r*64 + c4] = *(const float4*)(qg + (size_t)r*DD + c4);
    }
    for (int t = tid; t < 256*16; t += 256) {
        int r = t >> 4, c4 = (t & 15) * 4;
        float4 kv = *(const float4*)(kg + (size_t)r*DD + c4);
        Ks[r*65 + c4 + 0] = kv.x; Ks[r*65 + c4 + 1] = kv.y;
        Ks[r*65 + c4 + 2] = kv.z; Ks[r*65 + c4 + 3] = kv.w;
        *(float4*)&Vs[r*64 + c4] = *(const float4*)(vg + (size_t)r*DD + c4);
    }
    __syncthreads();

    int ty = tid >> 4, tx = tid & 15;
    float acc[4][16];
#pragma unroll
    for (int i = 0; i < 4; i++)
#pragma unroll
        for (int j = 0; j < 16; j++) acc[i][j] = 0.f;

#pragma unroll 4
    for (int k = 0; k < 64; k++) {
        float a[4];
#pragma unroll
        for (int i = 0; i < 4; i++) a[i] = Qs[(ty*4 + i)*64 + k];
#pragma unroll
        for (int j = 0; j < 16; j++) {
            float bb = Ks[(tx + 16*j)*65 + k];
#pragma unroll
            for (int i = 0; i < 4; i++) acc[i][j] += a[i]*bb;
        }
    }

    const float scale = 0.125f;
#pragma unroll
    for (int i = 0; i < 4; i++) {
        float mx = -1e30f;
#pragma unroll
        for (int j = 0; j < 16; j++) { acc[i][j] *= scale; mx = fmaxf(mx, acc[i][j]); }
#pragma unroll
        for (int o = 8; o > 0; o >>= 1) mx = fmaxf(mx, __shfl_xor_sync(0xffffffffu, mx, o));
        float s = 0.f;
#pragma unroll
        for (int j = 0; j < 16; j++) { acc[i][j] = __expf(acc[i][j] - mx); s += acc[i][j]; }
#pragma unroll
        for (int o = 8; o > 0; o >>= 1) s += __shfl_xor_sync(0xffffffffu, s, o);
        float inv = 1.0f / s;
#pragma unroll
        for (int j = 0; j < 16; j++) Ps[(ty*4 + i)*256 + tx + 16*j] = acc[i][j]*inv;
    }
    __syncthreads();

    float o[4][4];
#pragma unroll
    for (int i = 0; i < 4; i++)
#pragma unroll
        for (int j = 0; j < 4; j++) o[i][j] = 0.f;

#pragma unroll 4
    for (int m = 0; m < 256; m++) {
        float a[4];
#pragma unroll
        for (int i = 0; i < 4; i++) a[i] = Ps[(ty*4 + i)*256 + m];
        float4 bv = *(const float4*)&Vs[m*64 + tx*4];
#pragma unroll
        for (int i = 0; i < 4; i++) {
            o[i][0] += a[i]*bv.x; o[i][1] += a[i]*bv.y;
            o[i][2] += a[i]*bv.z; o[i][3] += a[i]*bv.w;
        }
    }
    float* og = g_o + ((size_t)(b*1024 + tile*64)) * DD + hh*64;
#pragma unroll
    for (int i = 0; i < 4; i++)
        *(float4*)(og + (size_t)(ty*4 + i)*DD + tx*4) = make_float4(o[i][0], o[i][1], o[i][2], o[i][3]);
}

// ---------------- host ----------------
static void gemm(const float* A, const float* B, float* C,
                 const float* bias, const float* res,
                 int M, int Nc, int K, int ldb, int ldc, int mode) {
    dim3 grid(Nc/128, M/128);
    k_gemm_tc<<<grid, 256, SMEM_GEMM>>>(A, B, C, bias, res, M, K, ldb, ldc, mode);
}

extern "C" void kernel_launch(void* const* d_in, const int* in_sizes, int n_in,
                              void* d_out, int out_size) {
    const float* x        = (const float*)d_in[0];
    const void*  eidx     = d_in[1];
    const float* cond     = (const float*)d_in[2];
    const float* bn_w     = (const float*)d_in[3];
    const float* bn_b     = (const float*)d_in[4];
    const float* gcn_in_w = (const float*)d_in[5];
    const float* gcn_in_b = (const float*)d_in[6];
    const float* gcn_out_w= (const float*)d_in[7];
    const float* gcn_out_b= (const float*)d_in[8];
    const float* Wq       = (const float*)d_in[9];
    const float* Wk       = (const float*)d_in[10];
    const float* Wv       = (const float*)d_in[11];
    const float* Wo       = (const float*)d_in[12];
    const float* ln2_w    = (const float*)d_in[13];
    const float* ln2_b    = (const float*)d_in[14];
    const float* ln3_w    = (const float*)d_in[15];
    const float* ln3_b    = (const float*)d_in[16];
    const float* geglu_w  = (const float*)d_in[17];
    const float* geglu_b  = (const float*)d_in[18];
    const float* ffo_w    = (const float*)d_in[19];
    const float* ffo_b    = (const float*)d_in[20];

    void *hb_, *lnb_, *qb_, *ob_, *kb_, *vb_, *fb_;
    cudaGetSymbolAddress(&hb_,  g_h);  cudaGetSymbolAddress(&lnb_, g_ln);
    cudaGetSymbolAddress(&qb_,  g_q);  cudaGetSymbolAddress(&ob_,  g_o);
    cudaGetSymbolAddress(&kb_,  g_k);  cudaGetSymbolAddress(&vb_,  g_v);
    cudaGetSymbolAddress(&fb_,  g_f);
    float* hb  = (float*)hb_;  float* lnb = (float*)lnb_;
    float* qb  = (float*)qb_;  float* ob  = (float*)ob_;
    float* kb  = (float*)kb_;  float* vb  = (float*)vb_;
    float* fb  = (float*)fb_;

    cudaFuncSetAttribute(k_attn,    cudaFuncAttributeMaxDynamicSharedMemorySize, AT_SMEM);
    cudaFuncSetAttribute(k_gemm_tc, cudaFuncAttributeMaxDynamicSharedMemorySize, SMEM_GEMM);

    const int NDv4 = NN*DD/4;

    // edges: detect dtype, convert, degrees, norms
    k_detect  <<<1, 32>>>((const int*)eidx);
    k_convert <<<EE/256, 256>>>(eidx);
    k_deg_init<<<NN/256, 256>>>();
    k_deg_edges<<<EE/256, 256>>>();
    k_dinv    <<<NN/256, 256>>>();
    k_norm    <<<EE/256, 256>>>();

    // BatchNorm -> g_ln
    k_bnstat_zero<<<1, 512>>>();
    k_bn_partial <<<64, 512>>>(x);
    k_bn_final   <<<1, 512>>>();
    k_bn_apply   <<<NDv4/256, 256>>>(x, bn_w, bn_b);

    // GCN in: g_q = bn @ W ; h = scatter + self + bias
    gemm(lnb, gcn_in_w, qb, nullptr, nullptr, NN, DD, DD, DD, DD, 0);
    k_zero    <<<4096, 256>>>((float4*)hb, NDv4);
    k_scatter <<<EE*128/256, 256>>>(qb, hb);
    k_selfbias<<<NDv4/256, 256>>>(qb, hb, gcn_in_b);

    for (int i = 0; i < LL; i++) {
        // attention block
        k_ln<<<NN/8, 256>>>(hb, lnb, ln2_w + i*DD, ln2_b + i*DD);
        gemm(lnb,  Wq + (size_t)i*DD*512,  qb, nullptr, nullptr, NN,  512, DD,  512, 512, 0);
        gemm(cond, Wk + (size_t)i*DCc*512, kb, nullptr, nullptr, NKV, 512, DCc, 512, 512, 0);
        gemm(cond, Wv + (size_t)i*DCc*512, vb, nullptr, nullptr, NKV, 512, DCc, 512, 512, 0);
        k_attn<<<dim3(BSb*HH, 16), 256, AT_SMEM>>>();
        gemm(ob, Wo + (size_t)i*512*DD, hb, nullptr, hb, NN, DD, 512, DD, DD, 0);  // h += o @ Wo
        // feed-forward (GEGLU), two passes, no u buffer
        k_ln<<<NN/8, 256>>>(hb, lnb, ln3_w + i*DD, ln3_b + i*DD);
        gemm(lnb, geglu_w + (size_t)i*DD*4096, fb,
             geglu_b + (size_t)i*4096, nullptr, NN, 2048, DD, 4096, 2048, 0);
        gemm(lnb, geglu_w + (size_t)i*DD*4096 + 2048, fb,
             geglu_b + (size_t)i*4096 + 2048, nullptr, NN, 2048, DD, 4096, 2048, 1);
        gemm(fb, ffo_w + (size_t)i*2048*DD, hb, ffo_b + (size_t)i*DD, hb, NN, DD, 2048, DD, DD, 0);
    }

    // GCN out + residual input
    gemm(hb, gcn_out_w, qb, nullptr, nullptr, NN, DD, DD, DD, DD, 0);
    k_zero   <<<4096, 256>>>((float4*)ob, NDv4);
    k_scatter<<<EE*128/256, 256>>>(qb, ob);
    k_final  <<<NDv4/256, 256>>>(ob, qb, gcn_out_b, x, (float*)d_out);
}

// round 5
// speedup vs baseline: 1.9632x; 1.1133x over previous
#include <cuda_runtime.h>
#include <cuda_bf16.h>
#include <math.h>
#include <stdint.h>

// ---------------- problem constants ----------------
#define NN   16384
#define DD   512
#define BSb  16
#define MMc  256
#define DCc  512
#define HH   8
#define DHh  64
#define LL   4
#define EE   262144
#define NKV  (BSb*MMc)
#define EPSf 1e-5f

// ---------------- transposed-weight scratch offsets (elements) ----------------
#define W_GCNIN   0u
#define W_GCNOUT  262144u
#define W_Q(i)    (524288u + (unsigned)(i)*262144u)
#define W_Kk(i)   (524288u + (unsigned)(4+(i))*262144u)
#define W_Vv(i)   (524288u + (unsigned)(8+(i))*262144u)
#define W_Oo(i)   (524288u + (unsigned)(12+(i))*262144u)
#define W_GEGLU(i) (4718592u + (unsigned)(i)*2097152u)
#define W_FFO(i)   (13107200u + (unsigned)(i)*1048576u)
#define W_TOTAL    17301504u

// ---------------- scratch (device globals) ----------------
__device__ float g_h [NN*DD];
__device__ float g_q [NN*DD];
__device__ float g_o [NN*DD];
__device__ float g_k [NKV*DD];
__device__ float g_v [NKV*DD];
__device__ float g_fb[NN*2048];     // GEGLU val (fp32)
__device__ __align__(256) __nv_bfloat16 g_phi[NN*DD],   g_plo[NN*DD];
__device__ __align__(256) __nv_bfloat16 g_fhi[NN*2048], g_flo[NN*2048];
__device__ __align__(256) __nv_bfloat16 g_chi[NKV*DD],  g_clo[NKV*DD];
__device__ __align__(256) __nv_bfloat16 g_whi[W_TOTAL], g_wlo[W_TOTAL];
__device__ float g_sum[DD], g_sq[DD], g_mu[DD], g_rstd[DD];
__device__ float g_deg[NN], g_dinv[NN];
__device__ float g_nrm[EE];
__device__ int   g_src[EE], g_dst[EE];
__device__ int   g_is64;

// ---------------- helpers ----------------
__device__ __forceinline__ uint32_t smem_u32(const void* p) {
    uint32_t a;
    asm("{ .reg .u64 t; cvta.to.shared.u64 t, %1; cvt.u32.u64 %0, t; }" : "=r"(a) : "l"(p));
    return a;
}
__device__ __forceinline__ void cp16(uint32_t dst, const void* src) {
    asm volatile("cp.async.cg.shared.global [%0], [%1], 16;" :: "r"(dst), "l"(src));
}
#define CP_COMMIT() asm volatile("cp.async.commit_group;" ::: "memory")
#define CP_WAIT(n)  asm volatile("cp.async.wait_group %0;" :: "n"(n) : "memory")

__device__ __forceinline__ void ldsm_x4(uint32_t addr, unsigned &r0, unsigned &r1, unsigned &r2, unsigned &r3) {
    asm volatile("ldmatrix.sync.aligned.m8n8.x4.shared.b16 {%0,%1,%2,%3}, [%4];"
        : "=r"(r0), "=r"(r1), "=r"(r2), "=r"(r3) : "r"(addr));
}
__device__ __forceinline__ void mma16816(float* c, const unsigned* a, unsigned b0, unsigned b1) {
    asm volatile("mma.sync.aligned.m16n8k16.row.col.f32.bf16.bf16.f32 "
        "{%0,%1,%2,%3},{%4,%5,%6,%7},{%8,%9},{%0,%1,%2,%3};"
        : "+f"(c[0]), "+f"(c[1]), "+f"(c[2]), "+f"(c[3])
        : "r"(a[0]), "r"(a[1]), "r"(a[2]), "r"(a[3]), "r"(b0), "r"(b1));
}
__device__ __forceinline__ void split_store(__nv_bfloat16* hi, __nv_bfloat16* lo, float4 v) {
    __nv_bfloat16 h0 = __float2bfloat16_rn(v.x);
    __nv_bfloat16 h1 = __float2bfloat16_rn(v.y);
    __nv_bfloat16 h2 = __float2bfloat16_rn(v.z);
    __nv_bfloat16 h3 = __float2bfloat16_rn(v.w);
    __nv_bfloat16 l0 = __float2bfloat16_rn(v.x - __bfloat162float(h0));
    __nv_bfloat16 l1 = __float2bfloat16_rn(v.y - __bfloat162float(h1));
    __nv_bfloat16 l2 = __float2bfloat16_rn(v.z - __bfloat162float(h2));
    __nv_bfloat16 l3 = __float2bfloat16_rn(v.w - __bfloat162float(h3));
    uint2 uh, ul;
    uh.x = (unsigned)__bfloat16_as_ushort(h0) | ((unsigned)__bfloat16_as_ushort(h1) << 16);
    uh.y = (unsigned)__bfloat16_as_ushort(h2) | ((unsigned)__bfloat16_as_ushort(h3) << 16);
    ul.x = (unsigned)__bfloat16_as_ushort(l0) | ((unsigned)__bfloat16_as_ushort(l1) << 16);
    ul.y = (unsigned)__bfloat16_as_ushort(l2) | ((unsigned)__bfloat16_as_ushort(l3) << 16);
    *(uint2*)hi = uh;
    *(uint2*)lo = ul;
}
__device__ __forceinline__ void split2(__nv_bfloat16* hi, __nv_bfloat16* lo, float a, float b) {
    __nv_bfloat16 h0 = __float2bfloat16_rn(a);
    __nv_bfloat16 h1 = __float2bfloat16_rn(b);
    __nv_bfloat16 l0 = __float2bfloat16_rn(a - __bfloat162float(h0));
    __nv_bfloat16 l1 = __float2bfloat16_rn(b - __bfloat162float(h1));
    unsigned uh = (unsigned)__bfloat16_as_ushort(h0) | ((unsigned)__bfloat16_as_ushort(h1) << 16);
    unsigned ul = (unsigned)__bfloat16_as_ushort(l0) | ((unsigned)__bfloat16_as_ushort(l1) << 16);
    *(unsigned*)hi = uh;
    *(unsigned*)lo = ul;
}

// ---------------- edge index prep ----------------
__global__ void k_detect(const int* e) {
    if (threadIdx.x == 0 && blockIdx.x == 0) {
        int nz = 0;
        for (int j = 0; j < 64; j++) nz += (e[2*j + 1] != 0);
        g_is64 = (nz == 0) ? 1 : 0;
    }
}
__global__ void k_convert(const void* eptr) {
    int i = blockIdx.x * 256 + threadIdx.x;
    if (i >= EE) return;
    if (g_is64) {
        const long long* p = (const long long*)eptr;
        g_src[i] = (int)p[i];  g_dst[i] = (int)p[EE + i];
    } else {
        const int* p = (const int*)eptr;
        g_src[i] = p[i];       g_dst[i] = p[EE + i];
    }
}
__global__ void k_deg_init() { int i = blockIdx.x*256 + threadIdx.x; if (i < NN) g_deg[i] = 1.0f; }
__global__ void k_deg_edges(){ int i = blockIdx.x*256 + threadIdx.x; if (i < EE) atomicAdd(&g_deg[g_dst[i]], 1.0f); }
__global__ void k_dinv()     { int i = blockIdx.x*256 + threadIdx.x; if (i < NN) g_dinv[i] = rsqrtf(g_deg[i]); }
__global__ void k_norm()     { int i = blockIdx.x*256 + threadIdx.x; if (i < EE) g_nrm[i] = g_dinv[g_src[i]] * g_dinv[g_dst[i]]; }

__global__ void k_zero(float4* p, int n4) {
    for (int i = blockIdx.x*blockDim.x + threadIdx.x; i < n4; i += gridDim.x*blockDim.x)
        p[i] = make_float4(0.f, 0.f, 0.f, 0.f);
}

// ---------------- weight transpose + bf16 split: Wt[n][k] = W[k][n] ----------------
__global__ void k_wt(const float* __restrict__ W, __nv_bfloat16* __restrict__ whi,
                     __nv_bfloat16* __restrict__ wlo, int K_, int N_) {
    __shared__ float ts[32][33];
    int tx = threadIdx.x & 31, ty = threadIdx.x >> 5;
    int bn = blockIdx.x, bk = blockIdx.y;
#pragma unroll
    for (int p = 0; p < 4; p++) {
        int kl = ty + p*8;
        ts[kl][tx] = W[(size_t)(bk*32 + kl)*N_ + bn*32 + tx];
    }
    __syncthreads();
#pragma unroll
    for (int p = 0; p < 4; p++) {
        int nl = ty + p*8;
        float v = ts[tx][nl];
        size_t oo = (size_t)(bn*32 + nl)*K_ + bk*32 + tx;
        __nv_bfloat16 h = __float2bfloat16_rn(v);
        whi[oo] = h;
        wlo[oo] = __float2bfloat16_rn(v - __bfloat162float(h));
    }
}

// ---------------- fp32 -> bf16 hi/lo elementwise split ----------------
__global__ void k_asplit(const float* __restrict__ src, __nv_bfloat16* __restrict__ hi,
                         __nv_bfloat16* __restrict__ lo, int n4) {
    int i = blockIdx.x*256 + threadIdx.x;
    if (i >= n4) return;
    split_store(hi + (size_t)i*4, lo + (size_t)i*4, ((const float4*)src)[i]);
}

// ---------------- BatchNorm ----------------
__global__ void k_bnstat_zero() { int c = threadIdx.x; g_sum[c] = 0.f; g_sq[c] = 0.f; }
__global__ void k_bn_partial(const float* __restrict__ x) {
    int c = threadIdx.x;
    int r0 = blockIdx.x * 256;
    float s = 0.f, q = 0.f;
    for (int r = 0; r < 256; r++) {
        float v = x[(size_t)(r0 + r)*DD + c];
        s += v; q += v*v;
    }
    atomicAdd(&g_sum[c], s); atomicAdd(&g_sq[c], q);
}
__global__ void k_bn_final() {
    int c = threadIdx.x;
    float mu = g_sum[c] * (1.0f/NN);
    g_mu[c] = mu;
    g_rstd[c] = rsqrtf(g_sq[c]*(1.0f/NN) - mu*mu + EPSf);
}
__global__ void k_bn_apply(const float* __restrict__ x, const float* __restrict__ w, const float* __restrict__ b) {
    int idx = blockIdx.x*256 + threadIdx.x;
    if (idx >= NN*DD/4) return;
    int c = (idx & 127) * 4;
    float4 xv = ((const float4*)x)[idx];
    float4 o;
    o.x = (xv.x - g_mu[c+0]) * g_rstd[c+0] * w[c+0] + b[c+0];
    o.y = (xv.y - g_mu[c+1]) * g_rstd[c+1] * w[c+1] + b[c+1];
    o.z = (xv.z - g_mu[c+2]) * g_rstd[c+2] * w[c+2] + b[c+2];
    o.w = (xv.w - g_mu[c+3]) * g_rstd[c+3] * w[c+3] + b[c+3];
    split_store(g_phi + (size_t)idx*4, g_plo + (size_t)idx*4, o);
}

// ---------------- LayerNorm -> bf16 hi/lo ----------------
__global__ void k_ln(const float* __restrict__ in, const float* __restrict__ w, const float* __restrict__ b) {
    int warp = threadIdx.x >> 5, lane = threadIdx.x & 31;
    int row = blockIdx.x * 8 + warp;
    const float4* xr = (const float4*)(in + (size_t)row * DD);
    float4 v[4]; float s = 0.f, q = 0.f;
#pragma unroll
    for (int j = 0; j < 4; j++) {
        v[j] = xr[j*32 + lane];
        s += v[j].x + v[j].y + v[j].z + v[j].w;
        q += v[j].x*v[j].x + v[j].y*v[j].y + v[j].z*v[j].z + v[j].w*v[j].w;
    }
#pragma unroll
    for (int o = 16; o > 0; o >>= 1) {
        s += __shfl_xor_sync(0xffffffffu, s, o);
        q += __shfl_xor_sync(0xffffffffu, q, o);
    }
    float mu = s * (1.0f/DD);
    float rs = rsqrtf(q*(1.0f/DD) - mu*mu + EPSf);
    const float4* w4 = (const float4*)w; const float4* b4 = (const float4*)b;
#pragma unroll
    for (int j = 0; j < 4; j++) {
        int c = j*32 + lane;
        float4 wv = w4[c], bv = b4[c], r;
        r.x = (v[j].x - mu)*rs*wv.x + bv.x;
        r.y = (v[j].y - mu)*rs*wv.y + bv.y;
        r.z = (v[j].z - mu)*rs*wv.z + bv.z;
        r.w = (v[j].w - mu)*rs*wv.w + bv.w;
        size_t oo = (size_t)row*DD + (size_t)c*4;
        split_store(g_phi + oo, g_plo + oo, r);
    }
}

// ================= bf16-split tensor-core GEMM (mma.sync, cp.async 4-stage) =================
// C[M x N] = A[M x K] @ W^T.  A: [M][K] bf16 hi/lo; B: W^T [N][K] bf16 hi/lo.
// CTA tile 128x128, BK=32, 256 threads (8 warps 2x4), warp tile 64x32.
// smem per stage: 4 matrices x 128 rows x 40 halves -> 40960 B; 4 stages = 160 KB.
// mode 0: C = A@B (+bias) (+res), fp32 out.
// mode 1: gate pass: g = A@B + bias; f = C_val * gelu(g) -> bf16 hi/lo (fhi/flo).
#define STG_B 40960
#define GSMEM (4*STG_B)

__global__ __launch_bounds__(256, 1) void k_gemm(
    const __nv_bfloat16* __restrict__ ahi, const __nv_bfloat16* __restrict__ alo,
    const __nv_bfloat16* __restrict__ bhi, const __nv_bfloat16* __restrict__ blo,
    float* __restrict__ C, const float* __restrict__ bias, const float* __restrict__ res,
    __nv_bfloat16* __restrict__ fhi, __nv_bfloat16* __restrict__ flo,
    int K, int ldc, int mode)
{
    extern __shared__ char dsm[];
    const uint32_t sb = smem_u32(dsm);
    const int tid = threadIdx.x;
    const int lane = tid & 31, warp = tid >> 5;
    const int wm = warp >> 2, wn = warp & 3;
    const int brow = blockIdx.y, bcol = blockIdx.x;
    const int KT = K >> 5;

    const __nv_bfloat16* sAh = ahi + (size_t)brow*128*K;
    const __nv_bfloat16* sAl = alo + (size_t)brow*128*K;
    const __nv_bfloat16* sBh = bhi + (size_t)bcol*128*K;
    const __nv_bfloat16* sBl = blo + (size_t)bcol*128*K;

    float acc[4][4][4];
#pragma unroll
    for (int mt = 0; mt < 4; mt++)
#pragma unroll
        for (int nt = 0; nt < 4; nt++)
#pragma unroll
            for (int e = 0; e < 4; e++) acc[mt][nt][e] = 0.f;

    // ---- async load of one 32-k tile into stage s ----
    auto load_stage = [&](int tile, int s) {
        uint32_t st = sb + s*STG_B;
        size_t koff = (size_t)tile*32;
#pragma unroll
        for (int it = 0; it < 2; it++) {
            int idx = tid + it*256;
            int row = idx >> 2, ch = idx & 3;
            uint32_t doff = (uint32_t)(row*80 + ch*16);
            size_t soff = (size_t)row*K + koff + ch*8;
            cp16(st +         doff, sAh + soff);
            cp16(st + 10240 + doff, sAl + soff);
            cp16(st + 20480 + doff, sBh + soff);
            cp16(st + 30720 + doff, sBl + soff);
        }
    };

    // prologue: stages 0..2
    load_stage(0, 0); CP_COMMIT();
    if (KT > 1) load_stage(1, 1);
    CP_COMMIT();
    if (KT > 2) load_stage(2, 2);
    CP_COMMIT();

    for (int kt = 0; kt < KT; kt++) {
        CP_WAIT(2);
        __syncthreads();
        if (kt + 3 < KT) load_stage(kt + 3, (kt + 3) & 3);
        CP_COMMIT();

        uint32_t st = sb + (kt & 3)*STG_B;
#pragma unroll
        for (int kh = 0; kh < 2; kh++) {
            unsigned Ah[4][4], Al[4][4], Bh[2][4], Bl[2][4];
            {
                int ar = wm*64 + (lane & 15);
                int ac = kh*16 + (lane >> 4)*8;
#pragma unroll
                for (int mt = 0; mt < 4; mt++) {
                    uint32_t off = (uint32_t)(((ar + mt*16)*40 + ac) * 2);
                    ldsm_x4(st + off,         Ah[mt][0], Ah[mt][1], Ah[mt][2], Ah[mt][3]);
                    ldsm_x4(st + 10240 + off, Al[mt][0], Al[mt][1], Al[mt][2], Al[mt][3]);
                }
            }
            {
                int mat = lane >> 3, rr = lane & 7;
                int brow_b = ((mat >> 1) & 1)*8 + rr;
                int bcol_b = kh*16 + (mat & 1)*8;
#pragma unroll
                for (int np = 0; np < 2; np++) {
                    int nr = wn*32 + np*16 + brow_b;
                    uint32_t off = (uint32_t)((nr*40 + bcol_b) * 2);
                    ldsm_x4(st + 20480 + off, Bh[np][0], Bh[np][1], Bh[np][2], Bh[np][3]);
                    ldsm_x4(st + 30720 + off, Bl[np][0], Bl[np][1], Bl[np][2], Bl[np][3]);
                }
            }
#pragma unroll
            for (int mt = 0; mt < 4; mt++)
#pragma unroll
                for (int np = 0; np < 2; np++)
#pragma unroll
                    for (int sub = 0; sub < 2; sub++) {
                        int nt = np*2 + sub;
                        mma16816(acc[mt][nt], Ah[mt], Bh[np][sub*2], Bh[np][sub*2+1]);
                        mma16816(acc[mt][nt], Ah[mt], Bl[np][sub*2], Bl[np][sub*2+1]);
                        mma16816(acc[mt][nt], Al[mt], Bh[np][sub*2], Bh[np][sub*2+1]);
                    }
        }
    }

    // ---- epilogue ----
    const int g = lane >> 2, tg = lane & 3;
#pragma unroll
    for (int mt = 0; mt < 4; mt++) {
#pragma unroll
        for (int nt = 0; nt < 4; nt++) {
            int lcol = wn*32 + nt*8 + tg*2;
            int gcol = bcol*128 + lcol;
            size_t off0 = ((size_t)brow*128 + wm*64 + mt*16 + g) * ldc + gcol;
            size_t off1 = off0 + 8*(size_t)ldc;
            float2 v0 = make_float2(acc[mt][nt][0], acc[mt][nt][1]);
            float2 v1 = make_float2(acc[mt][nt][2], acc[mt][nt][3]);
            if (bias) {
                float2 bv = *(const float2*)(bias + gcol);
                v0.x += bv.x; v0.y += bv.y; v1.x += bv.x; v1.y += bv.y;
            }
            if (mode == 1) {
                float2 a0 = *(const float2*)(C + off0);
                float2 a1 = *(const float2*)(C + off1);
                float f0 = a0.x * (0.5f*v0.x*(1.0f + erff(v0.x*0.70710678118654752f)));
                float f1 = a0.y * (0.5f*v0.y*(1.0f + erff(v0.y*0.70710678118654752f)));
                float f2 = a1.x * (0.5f*v1.x*(1.0f + erff(v1.x*0.70710678118654752f)));
                float f3 = a1.y * (0.5f*v1.y*(1.0f + erff(v1.y*0.70710678118654752f)));
                split2(fhi + off0, flo + off0, f0, f1);
                split2(fhi + off1, flo + off1, f2, f3);
            } else {
                if (res) {
                    float2 r0 = *(const float2*)(res + off0);
                    float2 r1 = *(const float2*)(res + off1);
                    v0.x += r0.x; v0.y += r0.y; v1.x += r1.x; v1.y += r1.y;
                }
                *(float2*)(C + off0) = v0;
                *(float2*)(C + off1) = v1;
            }
        }
    }
}

// ---------------- GCN scatter ----------------
__global__ void k_scatter(const float* __restrict__ g, float* __restrict__ out) {
    int idx = blockIdx.x*256 + threadIdx.x;
    if (idx >= EE*128) return;
    int e = idx >> 7;
    int c = (idx & 127) << 2;
    int s = g_src[e], d = g_dst[e];
    float nm = g_nrm[e];
    float4 gv = *(const float4*)(g + (size_t)s*DD + c);
    float* op = out + (size_t)d*DD + c;
    atomicAdd(op+0, gv.x*nm); atomicAdd(op+1, gv.y*nm);
    atomicAdd(op+2, gv.z*nm); atomicAdd(op+3, gv.w*nm);
}
__global__ void k_selfbias(const float* __restrict__ g, float* __restrict__ h, const float* __restrict__ b) {
    int idx = blockIdx.x*256 + threadIdx.x;
    if (idx >= NN*DD/4) return;
    int row = idx >> 7; int c = (idx & 127) * 4;
    float di = g_dinv[row]; float sn = di*di;
    float4 gv = ((const float4*)g)[idx];
    float4 hv = ((float4*)h)[idx];
    hv.x += gv.x*sn + b[c+0]; hv.y += gv.y*sn + b[c+1];
    hv.z += gv.z*sn + b[c+2]; hv.w += gv.w*sn + b[c+3];
    ((float4*)h)[idx] = hv;
}
__global__ void k_final(const float* __restrict__ scat, const float* __restrict__ g,
                        const float* __restrict__ b, const float* __restrict__ x,
                        float* __restrict__ out) {
    int idx = blockIdx.x*256 + threadIdx.x;
    if (idx >= NN*DD/4) return;
    int row = idx >> 7; int c = (idx & 127) * 4;
    float di = g_dinv[row]; float sn = di*di;
    float4 sv = ((const float4*)scat)[idx];
    float4 gv = ((const float4*)g)[idx];
    float4 xv = ((const float4*)x)[idx];
    float4 o;
    o.x = sv.x + gv.x*sn + b[c+0] + xv.x;
    o.y = sv.y + gv.y*sn + b[c+1] + xv.y;
    o.z = sv.z + gv.z*sn + b[c+2] + xv.z;
    o.w = sv.w + gv.w*sn + b[c+3] + xv.w;
    ((float4*)out)[idx] = o;
}

// ---------------- fused cross-attention (out -> bf16 hi/lo) ----------------
#define AT_SMEM ((64*64 + 256*65 + 256*64 + 64*256)*4)
__global__ __launch_bounds__(256) void k_attn() {
    extern __shared__ float sm[];
    float* Qs = sm;
    float* Ks = Qs + 64*64;
    float* Vs = Ks + 256*65;
    float* Ps = Vs + 256*64;

    int bh = blockIdx.x; int b = bh >> 3; int hh = bh & 7;
    int tile = blockIdx.y;
    int tid = threadIdx.x;

    const float* qg = g_q + ((size_t)(b*1024 + tile*64)) * DD + hh*64;
    const float* kg = g_k + ((size_t)(b*256)) * DD + hh*64;
    const float* vg = g_v + ((size_t)(b*256)) * DD + hh*64;

    for (int t = tid; t < 64*16; t += 256) {
        int r = t >> 4, c4 = (t & 15) * 4;
        *(float4*)&Qs[r*64 + c4] = *(const float4*)(qg + (size_t)r*DD + c4);
    }
    for (int t = tid; t < 256*16; t += 256) {
        int r = t >> 4, c4 = (t & 15) * 4;
        float4 kv = *(const float4*)(kg + (size_t)r*DD + c4);
        Ks[r*65 + c4 + 0] = kv.x; Ks[r*65 + c4 + 1] = kv.y;
        Ks[r*65 + c4 + 2] = kv.z; Ks[r*65 + c4 + 3] = kv.w;
        *(float4*)&Vs[r*64 + c4] = *(const float4*)(vg + (size_t)r*DD + c4);
    }
    __syncthreads();

    int ty = tid >> 4, tx = tid & 15;
    float acc[4][16];
#pragma unroll
    for (int i = 0; i < 4; i++)
#pragma unroll
        for (int j = 0; j < 16; j++) acc[i][j] = 0.f;

#pragma unroll 4
    for (int k = 0; k < 64; k++) {
        float a[4];
#pragma unroll
        for (int i = 0; i < 4; i++) a[i] = Qs[(ty*4 + i)*64 + k];
#pragma unroll
        for (int j = 0; j < 16; j++) {
            float bb = Ks[(tx + 16*j)*65 + k];
#pragma unroll
            for (int i = 0; i < 4; i++) acc[i][j] += a[i]*bb;
        }
    }

    const float scale = 0.125f;
#pragma unroll
    for (int i = 0; i < 4; i++) {
        float mx = -1e30f;
#pragma unroll
        for (int j = 0; j < 16; j++) { acc[i][j] *= scale; mx = fmaxf(mx, acc[i][j]); }
#pragma unroll
        for (int o = 8; o > 0; o >>= 1) mx = fmaxf(mx, __shfl_xor_sync(0xffffffffu, mx, o));
        float s = 0.f;
#pragma unroll
        for (int j = 0; j < 16; j++) { acc[i][j] = __expf(acc[i][j] - mx); s += acc[i][j]; }
#pragma unroll
        for (int o = 8; o > 0; o >>= 1) s += __shfl_xor_sync(0xffffffffu, s, o);
        float inv = 1.0f / s;
#pragma unroll
        for (int j = 0; j < 16; j++) Ps[(ty*4 + i)*256 + tx + 16*j] = acc[i][j]*inv;
    }
    __syncthreads();

    float o[4][4];
#pragma unroll
    for (int i = 0; i < 4; i++)
#pragma unroll
        for (int j = 0; j < 4; j++) o[i][j] = 0.f;

#pragma unroll 4
    for (int m = 0; m < 256; m++) {
        float a[4];
#pragma unroll
        for (int i = 0; i < 4; i++) a[i] = Ps[(ty*4 + i)*256 + m];
        float4 bv = *(const float4*)&Vs[m*64 + tx*4];
#pragma unroll
        for (int i = 0; i < 4; i++) {
            o[i][0] += a[i]*bv.x; o[i][1] += a[i]*bv.y;
            o[i][2] += a[i]*bv.z; o[i][3] += a[i]*bv.w;
        }
    }
#pragma unroll
    for (int i = 0; i < 4; i++) {
        size_t oo = ((size_t)(b*1024 + tile*64 + ty*4 + i))*DD + hh*64 + tx*4;
        split_store(g_phi + oo, g_plo + oo, make_float4(o[i][0], o[i][1], o[i][2], o[i][3]));
    }
}

// ---------------- host ----------------
static void gemm(const __nv_bfloat16* ahi, const __nv_bfloat16* alo,
                 const __nv_bfloat16* bhi, const __nv_bfloat16* blo,
                 float* C, const float* bias, const float* res,
                 __nv_bfloat16* fhi, __nv_bfloat16* flo,
                 int M, int Nc, int K, int ldc, int mode) {
    dim3 grid(Nc/128, M/128);
    k_gemm<<<grid, 256, GSMEM>>>(ahi, alo, bhi, blo, C, bias, res, fhi, flo, K, ldc, mode);
}

extern "C" void kernel_launch(void* const* d_in, const int* in_sizes, int n_in,
                              void* d_out, int out_size) {
    const float* x        = (const float*)d_in[0];
    const void*  eidx     = d_in[1];
    const float* cond     = (const float*)d_in[2];
    const float* bn_w     = (const float*)d_in[3];
    const float* bn_b     = (const float*)d_in[4];
    const float* gcn_in_w = (const float*)d_in[5];
    const float* gcn_in_b = (const float*)d_in[6];
    const float* gcn_out_w= (const float*)d_in[7];
    const float* gcn_out_b= (const float*)d_in[8];
    const float* Wq       = (const float*)d_in[9];
    const float* Wk       = (const float*)d_in[10];
    const float* Wv       = (const float*)d_in[11];
    const float* Wo       = (const float*)d_in[12];
    const float* ln2_w    = (const float*)d_in[13];
    const float* ln2_b    = (const float*)d_in[14];
    const float* ln3_w    = (const float*)d_in[15];
    const float* ln3_b    = (const float*)d_in[16];
    const float* geglu_w  = (const float*)d_in[17];
    const float* geglu_b  = (const float*)d_in[18];
    const float* ffo_w    = (const float*)d_in[19];
    const float* ffo_b    = (const float*)d_in[20];

    void *hb_, *qb_, *ob_, *kb_, *vb_, *fbb_, *phi_, *plo_, *fhi_, *flo_, *chi_, *clo_, *whi_, *wlo_;
    cudaGetSymbolAddress(&hb_,  g_h);   cudaGetSymbolAddress(&qb_,  g_q);
    cudaGetSymbolAddress(&ob_,  g_o);   cudaGetSymbolAddress(&kb_,  g_k);
    cudaGetSymbolAddress(&vb_,  g_v);   cudaGetSymbolAddress(&fbb_, g_fb);
    cudaGetSymbolAddress(&phi_, g_phi); cudaGetSymbolAddress(&plo_, g_plo);
    cudaGetSymbolAddress(&fhi_, g_fhi); cudaGetSymbolAddress(&flo_, g_flo);
    cudaGetSymbolAddress(&chi_, g_chi); cudaGetSymbolAddress(&clo_, g_clo);
    cudaGetSymbolAddress(&whi_, g_whi); cudaGetSymbolAddress(&wlo_, g_wlo);
    float* hb = (float*)hb_; float* qb = (float*)qb_; float* ob = (float*)ob_;
    float* kb = (float*)kb_; float* vb = (float*)vb_; float* fbb = (float*)fbb_;
    __nv_bfloat16* phi = (__nv_bfloat16*)phi_; __nv_bfloat16* plo = (__nv_bfloat16*)plo_;
    __nv_bfloat16* fhi = (__nv_bfloat16*)fhi_; __nv_bfloat16* flo = (__nv_bfloat16*)flo_;
    __nv_bfloat16* chi = (__nv_bfloat16*)chi_; __nv_bfloat16* clo = (__nv_bfloat16*)clo_;
    __nv_bfloat16* whi = (__nv_bfloat16*)whi_; __nv_bfloat16* wlo = (__nv_bfloat16*)wlo_;

    cudaFuncSetAttribute(k_attn, cudaFuncAttributeMaxDynamicSharedMemorySize, AT_SMEM);
    cudaFuncSetAttribute(k_gemm, cudaFuncAttributeMaxDynamicSharedMemorySize, GSMEM);

    const int NDv4 = NN*DD/4;

    // edges
    k_detect  <<<1, 32>>>((const int*)eidx);
    k_convert <<<EE/256, 256>>>(eidx);
    k_deg_init<<<NN/256, 256>>>();
    k_deg_edges<<<EE/256, 256>>>();
    k_dinv    <<<NN/256, 256>>>();
    k_norm    <<<EE/256, 256>>>();

    // weight transpose + split
    auto wt = [&](const float* W, unsigned off, int K_, int N_) {
        k_wt<<<dim3(N_/32, K_/32), 256>>>(W, whi + off, wlo + off, K_, N_);
    };
    wt(gcn_in_w,  W_GCNIN,  512, 512);
    wt(gcn_out_w, W_GCNOUT, 512, 512);
    for (int i = 0; i < LL; i++) {
        wt(Wq + (size_t)i*262144, W_Q(i),  512, 512);
        wt(Wk + (size_t)i*262144, W_Kk(i), 512, 512);
        wt(Wv + (size_t)i*262144, W_Vv(i), 512, 512);
        wt(Wo + (size_t)i*262144, W_Oo(i), 512, 512);
        wt(geglu_w + (size_t)i*2097152, W_GEGLU(i), 512, 4096);
        wt(ffo_w   + (size_t)i*1048576, W_FFO(i),  2048, 512);
    }
    // cond split (reused by all layers)
    k_asplit<<<(NKV*DD/4)/256, 256>>>(cond, chi, clo, NKV*DD/4);

    // BatchNorm -> phi/plo
    k_bnstat_zero<<<1, 512>>>();
    k_bn_partial <<<64, 512>>>(x);
    k_bn_final   <<<1, 512>>>();
    k_bn_apply   <<<NDv4/256, 256>>>(x, bn_w, bn_b);

    // GCN in
    gemm(phi, plo, whi + W_GCNIN, wlo + W_GCNIN, qb, nullptr, nullptr, nullptr, nullptr,
         NN, 512, 512, 512, 0);
    k_zero    <<<4096, 256>>>((float4*)hb, NDv4);
    k_scatter <<<EE*128/256, 256>>>(qb, hb);
    k_selfbias<<<NDv4/256, 256>>>(qb, hb, gcn_in_b);

    for (int i = 0; i < LL; i++) {
        // attention block
        k_ln<<<NN/8, 256>>>(hb, ln2_w + i*DD, ln2_b + i*DD);
        gemm(phi, plo, whi + W_Q(i),  wlo + W_Q(i),  qb, nullptr, nullptr, nullptr, nullptr,
             NN,  512, 512, 512, 0);
        gemm(chi, clo, whi + W_Kk(i), wlo + W_Kk(i), kb, nullptr, nullptr, nullptr, nullptr,
             NKV, 512, 512, 512, 0);
        gemm(chi, clo, whi + W_Vv(i), wlo + W_Vv(i), vb, nullptr, nullptr, nullptr, nullptr,
             NKV, 512, 512, 512, 0);
        k_attn<<<dim3(BSb*HH, 16), 256, AT_SMEM>>>();
        gemm(phi, plo, whi + W_Oo(i), wlo + W_Oo(i), hb, nullptr, hb, nullptr, nullptr,
             NN, 512, 512, 512, 0);                                // h += o @ Wo
        // feed-forward (GEGLU)
        k_ln<<<NN/8, 256>>>(hb, ln3_w + i*DD, ln3_b + i*DD);
        gemm(phi, plo, whi + W_GEGLU(i), wlo + W_GEGLU(i), fbb,
             geglu_b + (size_t)i*4096, nullptr, nullptr, nullptr,
             NN, 2048, 512, 2048, 0);                              // val
        gemm(phi, plo, whi + W_GEGLU(i) + 2048u*512u, wlo + W_GEGLU(i) + 2048u*512u, fbb,
             geglu_b + (size_t)i*4096 + 2048, nullptr, fhi, flo,
             NN, 2048, 512, 2048, 1);                              // f = val*gelu(gate) -> bf16
        gemm(fhi, flo, whi + W_FFO(i), wlo + W_FFO(i), hb,
             ffo_b + (size_t)i*DD, hb, nullptr, nullptr,
             NN, 512, 2048, 512, 0);                               // h += f @ W + b
    }

    // GCN out + residual input
    k_asplit<<<NDv4/256, 256>>>(hb, phi, plo, NDv4);
    gemm(phi, plo, whi + W_GCNOUT, wlo + W_GCNOUT, qb, nullptr, nullptr, nullptr, nullptr,
         NN, 512, 512, 512, 0);
    k_zero   <<<4096, 256>>>((float4*)ob, NDv4);
    k_scatter<<<EE*128/256, 256>>>(qb, ob);
    k_final  <<<NDv4/256, 256>>>(ob, qb, gcn_out_b, x, (float*)d_out);
}

// round 6
// speedup vs baseline: 2.1057x; 1.0726x over previous
#include <cuda_runtime.h>
#include <cuda_bf16.h>
#include <math.h>
#include <stdint.h>

// ---------------- problem constants ----------------
#define NN   16384
#define DD   512
#define BSb  16
#define MMc  256
#define DCc  512
#define HH   8
#define DHh  64
#define LL   4
#define EE   262144
#define NKV  (BSb*MMc)
#define EPSf 1e-5f

// ---------------- transposed-weight scratch offsets (elements) ----------------
#define W_GCNIN   0u
#define W_GCNOUT  262144u
#define W_Q(i)    (524288u + (unsigned)(i)*262144u)
#define W_Kk(i)   (524288u + (unsigned)(4+(i))*262144u)
#define W_Vv(i)   (524288u + (unsigned)(8+(i))*262144u)
#define W_Oo(i)   (524288u + (unsigned)(12+(i))*262144u)
#define W_GEGLU(i) (4718592u + (unsigned)(i)*2097152u)
#define W_FFO(i)   (13107200u + (unsigned)(i)*1048576u)
#define W_TOTAL    17301504u

// ---------------- scratch (device globals) ----------------
__device__ float g_h [NN*DD];
__device__ float g_q [NN*DD];
__device__ float g_k [NKV*DD];
__device__ float g_v [NKV*DD];
__device__ float g_fb[NN*2048];     // GEGLU val (fp32)
__device__ __align__(256) __nv_bfloat16 g_phi[NN*DD],   g_plo[NN*DD];
__device__ __align__(256) __nv_bfloat16 g_fhi[NN*2048], g_flo[NN*2048];
__device__ __align__(256) __nv_bfloat16 g_chi[NKV*DD],  g_clo[NKV*DD];
__device__ __align__(256) __nv_bfloat16 g_whi[W_TOTAL], g_wlo[W_TOTAL];
__device__ float g_sum[DD], g_sq[DD], g_mu[DD], g_rstd[DD];
__device__ float g_deg[NN], g_dinv[NN];
__device__ int   g_src[EE], g_dst[EE];
__device__ int   g_rof[NN+1];       // CSR row offsets (edges only, no self loops)
__device__ int   g_cur[NN];         // placement cursors
__device__ int   g_esrc[EE];        // CSR src per slot
__device__ float g_enrm[EE];        // CSR norm per slot
__device__ int   g_is64;

// ---------------- helpers ----------------
__device__ __forceinline__ uint32_t smem_u32(const void* p) {
    uint32_t a;
    asm("{ .reg .u64 t; cvta.to.shared.u64 t, %1; cvt.u32.u64 %0, t; }" : "=r"(a) : "l"(p));
    return a;
}
__device__ __forceinline__ void cp16(uint32_t dst, const void* src) {
    asm volatile("cp.async.cg.shared.global [%0], [%1], 16;" :: "r"(dst), "l"(src));
}
#define CP_COMMIT() asm volatile("cp.async.commit_group;" ::: "memory")
#define CP_WAIT(n)  asm volatile("cp.async.wait_group %0;" :: "n"(n) : "memory")

__device__ __forceinline__ void ldsm_x4(uint32_t addr, unsigned &r0, unsigned &r1, unsigned &r2, unsigned &r3) {
    asm volatile("ldmatrix.sync.aligned.m8n8.x4.shared.b16 {%0,%1,%2,%3}, [%4];"
        : "=r"(r0), "=r"(r1), "=r"(r2), "=r"(r3) : "r"(addr));
}
__device__ __forceinline__ void mma16816(float* c, const unsigned* a, unsigned b0, unsigned b1) {
    asm volatile("mma.sync.aligned.m16n8k16.row.col.f32.bf16.bf16.f32 "
        "{%0,%1,%2,%3},{%4,%5,%6,%7},{%8,%9},{%0,%1,%2,%3};"
        : "+f"(c[0]), "+f"(c[1]), "+f"(c[2]), "+f"(c[3])
        : "r"(a[0]), "r"(a[1]), "r"(a[2]), "r"(a[3]), "r"(b0), "r"(b1));
}
__device__ __forceinline__ void split_store(__nv_bfloat16* hi, __nv_bfloat16* lo, float4 v) {
    __nv_bfloat16 h0 = __float2bfloat16_rn(v.x);
    __nv_bfloat16 h1 = __float2bfloat16_rn(v.y);
    __nv_bfloat16 h2 = __float2bfloat16_rn(v.z);
    __nv_bfloat16 h3 = __float2bfloat16_rn(v.w);
    __nv_bfloat16 l0 = __float2bfloat16_rn(v.x - __bfloat162float(h0));
    __nv_bfloat16 l1 = __float2bfloat16_rn(v.y - __bfloat162float(h1));
    __nv_bfloat16 l2 = __float2bfloat16_rn(v.z - __bfloat162float(h2));
    __nv_bfloat16 l3 = __float2bfloat16_rn(v.w - __bfloat162float(h3));
    uint2 uh, ul;
    uh.x = (unsigned)__bfloat16_as_ushort(h0) | ((unsigned)__bfloat16_as_ushort(h1) << 16);
    uh.y = (unsigned)__bfloat16_as_ushort(h2) | ((unsigned)__bfloat16_as_ushort(h3) << 16);
    ul.x = (unsigned)__bfloat16_as_ushort(l0) | ((unsigned)__bfloat16_as_ushort(l1) << 16);
    ul.y = (unsigned)__bfloat16_as_ushort(l2) | ((unsigned)__bfloat16_as_ushort(l3) << 16);
    *(uint2*)hi = uh;
    *(uint2*)lo = ul;
}
__device__ __forceinline__ void split2(__nv_bfloat16* hi, __nv_bfloat16* lo, float a, float b) {
    __nv_bfloat16 h0 = __float2bfloat16_rn(a);
    __nv_bfloat16 h1 = __float2bfloat16_rn(b);
    __nv_bfloat16 l0 = __float2bfloat16_rn(a - __bfloat162float(h0));
    __nv_bfloat16 l1 = __float2bfloat16_rn(b - __bfloat162float(h1));
    unsigned uh = (unsigned)__bfloat16_as_ushort(h0) | ((unsigned)__bfloat16_as_ushort(h1) << 16);
    unsigned ul = (unsigned)__bfloat16_as_ushort(l0) | ((unsigned)__bfloat16_as_ushort(l1) << 16);
    *(unsigned*)hi = uh;
    *(unsigned*)lo = ul;
}

// ---------------- edge index prep ----------------
__global__ void k_detect(const int* e) {
    if (threadIdx.x == 0 && blockIdx.x == 0) {
        int nz = 0;
        for (int j = 0; j < 64; j++) nz += (e[2*j + 1] != 0);
        g_is64 = (nz == 0) ? 1 : 0;
    }
}
__global__ void k_convert(const void* eptr) {
    int i = blockIdx.x * 256 + threadIdx.x;
    if (i >= EE) return;
    if (g_is64) {
        const long long* p = (const long long*)eptr;
        g_src[i] = (int)p[i];  g_dst[i] = (int)p[EE + i];
    } else {
        const int* p = (const int*)eptr;
        g_src[i] = p[i];       g_dst[i] = p[EE + i];
    }
}
__global__ void k_deg_init() { int i = blockIdx.x*256 + threadIdx.x; if (i < NN) { g_deg[i] = 1.0f; g_cur[i] = 0; } }
__global__ void k_deg_edges(){ int i = blockIdx.x*256 + threadIdx.x; if (i < EE) atomicAdd(&g_deg[g_dst[i]], 1.0f); }
__global__ void k_dinv()     { int i = blockIdx.x*256 + threadIdx.x; if (i < NN) g_dinv[i] = rsqrtf(g_deg[i]); }

// ---- CSR build: prefix scan (1 block, 512 thr x 32 vals) + place ----
__global__ void k_scan() {
    __shared__ int ps[512];
    int t = threadIdx.x;
    int base = t * 32;
    int loc[32];
    int s = 0;
#pragma unroll
    for (int j = 0; j < 32; j++) { loc[j] = s; s += (int)g_deg[base + j] - 1; }
    ps[t] = s;
    __syncthreads();
    for (int off = 1; off < 512; off <<= 1) {
        int v = (t >= off) ? ps[t - off] : 0;
        __syncthreads();
        ps[t] += v;
        __syncthreads();
    }
    int prev = (t == 0) ? 0 : ps[t-1];
#pragma unroll
    for (int j = 0; j < 32; j++) g_rof[base + j] = prev + loc[j];
    if (t == 511) g_rof[NN] = ps[511];
}
__global__ void k_place() {
    int e = blockIdx.x*256 + threadIdx.x;
    if (e >= EE) return;
    int s = g_src[e], d = g_dst[e];
    int pos = g_rof[d] + atomicAdd(&g_cur[d], 1);
    g_esrc[pos] = s;
    g_enrm[pos] = g_dinv[s] * g_dinv[d];
}

// ---- GCN gather: out[row] = sum_e g[src]*nrm + g[row]*dinv^2 + bias (+xres) ----
__global__ __launch_bounds__(128) void k_gather(const float* __restrict__ g, float* __restrict__ out,
                                                const float* __restrict__ bias, const float* __restrict__ xres) {
    int row = blockIdx.x;
    int c = threadIdx.x * 4;
    int beg = g_rof[row], end = g_rof[row+1];
    float4 acc = make_float4(0.f, 0.f, 0.f, 0.f);
    for (int e = beg; e < end; e++) {
        int s = g_esrc[e];
        float nm = g_enrm[e];
        float4 gv = *(const float4*)(g + (size_t)s*DD + c);
        acc.x += gv.x*nm; acc.y += gv.y*nm; acc.z += gv.z*nm; acc.w += gv.w*nm;
    }
    float di = g_dinv[row]; float sn = di*di;
    float4 gv = *(const float4*)(g + (size_t)row*DD + c);
    float4 bv = *(const float4*)(bias + c);
    acc.x += gv.x*sn + bv.x; acc.y += gv.y*sn + bv.y;
    acc.z += gv.z*sn + bv.z; acc.w += gv.w*sn + bv.w;
    if (xres) {
        float4 xv = *(const float4*)(xres + (size_t)row*DD + c);
        acc.x += xv.x; acc.y += xv.y; acc.z += xv.z; acc.w += xv.w;
    }
    *(float4*)(out + (size_t)row*DD + c) = acc;
}

// ---------------- weight transpose + bf16 split: Wt[n][k] = W[k][n] ----------------
__global__ void k_wt(const float* __restrict__ W, __nv_bfloat16* __restrict__ whi,
                     __nv_bfloat16* __restrict__ wlo, int K_, int N_) {
    __shared__ float ts[32][33];
    int tx = threadIdx.x & 31, ty = threadIdx.x >> 5;
    int bn = blockIdx.x, bk = blockIdx.y;
#pragma unroll
    for (int p = 0; p < 4; p++) {
        int kl = ty + p*8;
        ts[kl][tx] = W[(size_t)(bk*32 + kl)*N_ + bn*32 + tx];
    }
    __syncthreads();
#pragma unroll
    for (int p = 0; p < 4; p++) {
        int nl = ty + p*8;
        float v = ts[tx][nl];
        size_t oo = (size_t)(bn*32 + nl)*K_ + bk*32 + tx;
        __nv_bfloat16 h = __float2bfloat16_rn(v);
        whi[oo] = h;
        wlo[oo] = __float2bfloat16_rn(v - __bfloat162float(h));
    }
}

// ---------------- fp32 -> bf16 hi/lo elementwise split ----------------
__global__ void k_asplit(const float* __restrict__ src, __nv_bfloat16* __restrict__ hi,
                         __nv_bfloat16* __restrict__ lo, int n4) {
    int i = blockIdx.x*256 + threadIdx.x;
    if (i >= n4) return;
    split_store(hi + (size_t)i*4, lo + (size_t)i*4, ((const float4*)src)[i]);
}

// ---------------- BatchNorm ----------------
__global__ void k_bnstat_zero() { int c = threadIdx.x; g_sum[c] = 0.f; g_sq[c] = 0.f; }
__global__ void k_bn_partial(const float* __restrict__ x) {
    int c = threadIdx.x;
    int r0 = blockIdx.x * 256;
    float s = 0.f, q = 0.f;
    for (int r = 0; r < 256; r++) {
        float v = x[(size_t)(r0 + r)*DD + c];
        s += v; q += v*v;
    }
    atomicAdd(&g_sum[c], s); atomicAdd(&g_sq[c], q);
}
__global__ void k_bn_final() {
    int c = threadIdx.x;
    float mu = g_sum[c] * (1.0f/NN);
    g_mu[c] = mu;
    g_rstd[c] = rsqrtf(g_sq[c]*(1.0f/NN) - mu*mu + EPSf);
}
__global__ void k_bn_apply(const float* __restrict__ x, const float* __restrict__ w, const float* __restrict__ b) {
    int idx = blockIdx.x*256 + threadIdx.x;
    if (idx >= NN*DD/4) return;
    int c = (idx & 127) * 4;
    float4 xv = ((const float4*)x)[idx];
    float4 o;
    o.x = (xv.x - g_mu[c+0]) * g_rstd[c+0] * w[c+0] + b[c+0];
    o.y = (xv.y - g_mu[c+1]) * g_rstd[c+1] * w[c+1] + b[c+1];
    o.z = (xv.z - g_mu[c+2]) * g_rstd[c+2] * w[c+2] + b[c+2];
    o.w = (xv.w - g_mu[c+3]) * g_rstd[c+3] * w[c+3] + b[c+3];
    split_store(g_phi + (size_t)idx*4, g_plo + (size_t)idx*4, o);
}

// ---------------- LayerNorm -> bf16 hi/lo ----------------
__global__ void k_ln(const float* __restrict__ in, const float* __restrict__ w, const float* __restrict__ b) {
    int warp = threadIdx.x >> 5, lane = threadIdx.x & 31;
    int row = blockIdx.x * 8 + warp;
    const float4* xr = (const float4*)(in + (size_t)row * DD);
    float4 v[4]; float s = 0.f, q = 0.f;
#pragma unroll
    for (int j = 0; j < 4; j++) {
        v[j] = xr[j*32 + lane];
        s += v[j].x + v[j].y + v[j].z + v[j].w;
        q += v[j].x*v[j].x + v[j].y*v[j].y + v[j].z*v[j].z + v[j].w*v[j].w;
    }
#pragma unroll
    for (int o = 16; o > 0; o >>= 1) {
        s += __shfl_xor_sync(0xffffffffu, s, o);
        q += __shfl_xor_sync(0xffffffffu, q, o);
    }
    float mu = s * (1.0f/DD);
    float rs = rsqrtf(q*(1.0f/DD) - mu*mu + EPSf);
    const float4* w4 = (const float4*)w; const float4* b4 = (const float4*)b;
#pragma unroll
    for (int j = 0; j < 4; j++) {
        int c = j*32 + lane;
        float4 wv = w4[c], bv = b4[c], r;
        r.x = (v[j].x - mu)*rs*wv.x + bv.x;
        r.y = (v[j].y - mu)*rs*wv.y + bv.y;
        r.z = (v[j].z - mu)*rs*wv.z + bv.z;
        r.w = (v[j].w - mu)*rs*wv.w + bv.w;
        size_t oo = (size_t)row*DD + (size_t)c*4;
        split_store(g_phi + oo, g_plo + oo, r);
    }
}

// ================= bf16-split tensor-core GEMM (mma.sync, cp.async 4-stage) =================
#define STG_B 40960
#define GSMEM (4*STG_B)

__global__ __launch_bounds__(256, 1) void k_gemm(
    const __nv_bfloat16* __restrict__ ahi, const __nv_bfloat16* __restrict__ alo,
    const __nv_bfloat16* __restrict__ bhi, const __nv_bfloat16* __restrict__ blo,
    float* __restrict__ C, const float* __restrict__ bias, const float* __restrict__ res,
    __nv_bfloat16* __restrict__ fhi, __nv_bfloat16* __restrict__ flo,
    int K, int ldc, int mode)
{
    extern __shared__ char dsm[];
    const uint32_t sb = smem_u32(dsm);
    const int tid = threadIdx.x;
    const int lane = tid & 31, warp = tid >> 5;
    const int wm = warp >> 2, wn = warp & 3;
    const int brow = blockIdx.y, bcol = blockIdx.x;
    const int KT = K >> 5;

    const __nv_bfloat16* sAh = ahi + (size_t)brow*128*K;
    const __nv_bfloat16* sAl = alo + (size_t)brow*128*K;
    const __nv_bfloat16* sBh = bhi + (size_t)bcol*128*K;
    const __nv_bfloat16* sBl = blo + (size_t)bcol*128*K;

    float acc[4][4][4];
#pragma unroll
    for (int mt = 0; mt < 4; mt++)
#pragma unroll
        for (int nt = 0; nt < 4; nt++)
#pragma unroll
            for (int e = 0; e < 4; e++) acc[mt][nt][e] = 0.f;

    auto load_stage = [&](int tile, int s) {
        uint32_t st = sb + s*STG_B;
        size_t koff = (size_t)tile*32;
#pragma unroll
        for (int it = 0; it < 2; it++) {
            int idx = tid + it*256;
            int row = idx >> 2, ch = idx & 3;
            uint32_t doff = (uint32_t)(row*80 + ch*16);
            size_t soff = (size_t)row*K + koff + ch*8;
            cp16(st +         doff, sAh + soff);
            cp16(st + 10240 + doff, sAl + soff);
            cp16(st + 20480 + doff, sBh + soff);
            cp16(st + 30720 + doff, sBl + soff);
        }
    };

    load_stage(0, 0); CP_COMMIT();
    if (KT > 1) load_stage(1, 1);
    CP_COMMIT();
    if (KT > 2) load_stage(2, 2);
    CP_COMMIT();

    for (int kt = 0; kt < KT; kt++) {
        CP_WAIT(2);
        __syncthreads();
        if (kt + 3 < KT) load_stage(kt + 3, (kt + 3) & 3);
        CP_COMMIT();

        uint32_t st = sb + (kt & 3)*STG_B;
#pragma unroll
        for (int kh = 0; kh < 2; kh++) {
            unsigned Ah[4][4], Al[4][4], Bh[2][4], Bl[2][4];
            {
                int ar = wm*64 + (lane & 15);
                int ac = kh*16 + (lane >> 4)*8;
#pragma unroll
                for (int mt = 0; mt < 4; mt++) {
                    uint32_t off = (uint32_t)(((ar + mt*16)*40 + ac) * 2);
                    ldsm_x4(st + off,         Ah[mt][0], Ah[mt][1], Ah[mt][2], Ah[mt][3]);
                    ldsm_x4(st + 10240 + off, Al[mt][0], Al[mt][1], Al[mt][2], Al[mt][3]);
                }
            }
            {
                int mat = lane >> 3, rr = lane & 7;
                int brow_b = ((mat >> 1) & 1)*8 + rr;
                int bcol_b = kh*16 + (mat & 1)*8;
#pragma unroll
                for (int np = 0; np < 2; np++) {
                    int nr = wn*32 + np*16 + brow_b;
                    uint32_t off = (uint32_t)((nr*40 + bcol_b) * 2);
                    ldsm_x4(st + 20480 + off, Bh[np][0], Bh[np][1], Bh[np][2], Bh[np][3]);
                    ldsm_x4(st + 30720 + off, Bl[np][0], Bl[np][1], Bl[np][2], Bl[np][3]);
                }
            }
#pragma unroll
            for (int mt = 0; mt < 4; mt++)
#pragma unroll
                for (int np = 0; np < 2; np++)
#pragma unroll
                    for (int sub = 0; sub < 2; sub++) {
                        int nt = np*2 + sub;
                        mma16816(acc[mt][nt], Ah[mt], Bh[np][sub*2], Bh[np][sub*2+1]);
                        mma16816(acc[mt][nt], Ah[mt], Bl[np][sub*2], Bl[np][sub*2+1]);
                        mma16816(acc[mt][nt], Al[mt], Bh[np][sub*2], Bh[np][sub*2+1]);
                    }
        }
    }

    // ---- epilogue ----
    const int g = lane >> 2, tg = lane & 3;
#pragma unroll
    for (int mt = 0; mt < 4; mt++) {
#pragma unroll
        for (int nt = 0; nt < 4; nt++) {
            int lcol = wn*32 + nt*8 + tg*2;
            int gcol = bcol*128 + lcol;
            size_t off0 = ((size_t)brow*128 + wm*64 + mt*16 + g) * ldc + gcol;
            size_t off1 = off0 + 8*(size_t)ldc;
            float2 v0 = make_float2(acc[mt][nt][0], acc[mt][nt][1]);
            float2 v1 = make_float2(acc[mt][nt][2], acc[mt][nt][3]);
            if (bias) {
                float2 bv = *(const float2*)(bias + gcol);
                v0.x += bv.x; v0.y += bv.y; v1.x += bv.x; v1.y += bv.y;
            }
            if (mode == 1) {
                float2 a0 = *(const float2*)(C + off0);
                float2 a1 = *(const float2*)(C + off1);
                float f0 = a0.x * (0.5f*v0.x*(1.0f + erff(v0.x*0.70710678118654752f)));
                float f1 = a0.y * (0.5f*v0.y*(1.0f + erff(v0.y*0.70710678118654752f)));
                float f2 = a1.x * (0.5f*v1.x*(1.0f + erff(v1.x*0.70710678118654752f)));
                float f3 = a1.y * (0.5f*v1.y*(1.0f + erff(v1.y*0.70710678118654752f)));
                split2(fhi + off0, flo + off0, f0, f1);
                split2(fhi + off1, flo + off1, f2, f3);
            } else {
                if (res) {
                    float2 r0 = *(const float2*)(res + off0);
                    float2 r1 = *(const float2*)(res + off1);
                    v0.x += r0.x; v0.y += r0.y; v1.x += r1.x; v1.y += r1.y;
                }
                *(float2*)(C + off0) = v0;
                *(float2*)(C + off1) = v1;
            }
        }
    }
}

// ---------------- fused cross-attention (out -> bf16 hi/lo) ----------------
#define AT_SMEM ((64*64 + 256*65 + 256*64 + 64*256)*4)
__global__ __launch_bounds__(256) void k_attn() {
    extern __shared__ float sm[];
    float* Qs = sm;
    float* Ks = Qs + 64*64;
    float* Vs = Ks + 256*65;
    float* Ps = Vs + 256*64;

    int bh = blockIdx.x; int b = bh >> 3; int hh = bh & 7;
    int tile = blockIdx.y;
    int tid = threadIdx.x;

    const float* qg = g_q + ((size_t)(b*1024 + tile*64)) * DD + hh*64;
    const float* kg = g_k + ((size_t)(b*256)) * DD + hh*64;
    const float* vg = g_v + ((size_t)(b*256)) * DD + hh*64;

    for (int t = tid; t < 64*16; t += 256) {
        int r = t >> 4, c4 = (t & 15) * 4;
        *(float4*)&Qs[r*64 + c4] = *(const float4*)(qg + (size_t)r*DD + c4);
    }
    for (int t = tid; t < 256*16; t += 256) {
        int r = t >> 4, c4 = (t & 15) * 4;
        float4 kv = *(const float4*)(kg + (size_t)r*DD + c4);
        Ks[r*65 + c4 + 0] = kv.x; Ks[r*65 + c4 + 1] = kv.y;
        Ks[r*65 + c4 + 2] = kv.z; Ks[r*65 + c4 + 3] = kv.w;
        *(float4*)&Vs[r*64 + c4] = *(const float4*)(vg + (size_t)r*DD + c4);
    }
    __syncthreads();

    int ty = tid >> 4, tx = tid & 15;
    float acc[4][16];
#pragma unroll
    for (int i = 0; i < 4; i++)
#pragma unroll
        for (int j = 0; j < 16; j++) acc[i][j] = 0.f;

#pragma unroll 4
    for (int k = 0; k < 64; k++) {
        float a[4];
#pragma unroll
        for (int i = 0; i < 4; i++) a[i] = Qs[(ty*4 + i)*64 + k];
#pragma unroll
        for (int j = 0; j < 16; j++) {
            float bb = Ks[(tx + 16*j)*65 + k];
#pragma unroll
            for (int i = 0; i < 4; i++) acc[i][j] += a[i]*bb;
        }
    }

    const float scale = 0.125f;
#pragma unroll
    for (int i = 0; i < 4; i++) {
        float mx = -1e30f;
#pragma unroll
        for (int j = 0; j < 16; j++) { acc[i][j] *= scale; mx = fmaxf(mx, acc[i][j]); }
#pragma unroll
        for (int o = 8; o > 0; o >>= 1) mx = fmaxf(mx, __shfl_xor_sync(0xffffffffu, mx, o));
        float s = 0.f;
#pragma unroll
        for (int j = 0; j < 16; j++) { acc[i][j] = __expf(acc[i][j] - mx); s += acc[i][j]; }
#pragma unroll
        for (int o = 8; o > 0; o >>= 1) s += __shfl_xor_sync(0xffffffffu, s, o);
        float inv = 1.0f / s;
#pragma unroll
        for (int j = 0; j < 16; j++) Ps[(ty*4 + i)*256 + tx + 16*j] = acc[i][j]*inv;
    }
    __syncthreads();

    float o[4][4];
#pragma unroll
    for (int i = 0; i < 4; i++)
#pragma unroll
        for (int j = 0; j < 4; j++) o[i][j] = 0.f;

#pragma unroll 4
    for (int m = 0; m < 256; m++) {
        float a[4];
#pragma unroll
        for (int i = 0; i < 4; i++) a[i] = Ps[(ty*4 + i)*256 + m];
        float4 bv = *(const float4*)&Vs[m*64 + tx*4];
#pragma unroll
        for (int i = 0; i < 4; i++) {
            o[i][0] += a[i]*bv.x; o[i][1] += a[i]*bv.y;
            o[i][2] += a[i]*bv.z; o[i][3] += a[i]*bv.w;
        }
    }
#pragma unroll
    for (int i = 0; i < 4; i++) {
        size_t oo = ((size_t)(b*1024 + tile*64 + ty*4 + i))*DD + hh*64 + tx*4;
        split_store(g_phi + oo, g_plo + oo, make_float4(o[i][0], o[i][1], o[i][2], o[i][3]));
    }
}

// ---------------- host ----------------
static void gemm(const __nv_bfloat16* ahi, const __nv_bfloat16* alo,
                 const __nv_bfloat16* bhi, const __nv_bfloat16* blo,
                 float* C, const float* bias, const float* res,
                 __nv_bfloat16* fhi, __nv_bfloat16* flo,
                 int M, int Nc, int K, int ldc, int mode) {
    dim3 grid(Nc/128, M/128);
    k_gemm<<<grid, 256, GSMEM>>>(ahi, alo, bhi, blo, C, bias, res, fhi, flo, K, ldc, mode);
}

extern "C" void kernel_launch(void* const* d_in, const int* in_sizes, int n_in,
                              void* d_out, int out_size) {
    const float* x        = (const float*)d_in[0];
    const void*  eidx     = d_in[1];
    const float* cond     = (const float*)d_in[2];
    const float* bn_w     = (const float*)d_in[3];
    const float* bn_b     = (const float*)d_in[4];
    const float* gcn_in_w = (const float*)d_in[5];
    const float* gcn_in_b = (const float*)d_in[6];
    const float* gcn_out_w= (const float*)d_in[7];
    const float* gcn_out_b= (const float*)d_in[8];
    const float* Wq       = (const float*)d_in[9];
    const float* Wk       = (const float*)d_in[10];
    const float* Wv       = (const float*)d_in[11];
    const float* Wo       = (const float*)d_in[12];
    const float* ln2_w    = (const float*)d_in[13];
    const float* ln2_b    = (const float*)d_in[14];
    const float* ln3_w    = (const float*)d_in[15];
    const float* ln3_b    = (const float*)d_in[16];
    const float* geglu_w  = (const float*)d_in[17];
    const float* geglu_b  = (const float*)d_in[18];
    const float* ffo_w    = (const float*)d_in[19];
    const float* ffo_b    = (const float*)d_in[20];

    void *hb_, *qb_, *kb_, *vb_, *fbb_, *phi_, *plo_, *fhi_, *flo_, *chi_, *clo_, *whi_, *wlo_;
    cudaGetSymbolAddress(&hb_,  g_h);   cudaGetSymbolAddress(&qb_,  g_q);
    cudaGetSymbolAddress(&kb_,  g_k);   cudaGetSymbolAddress(&vb_,  g_v);
    cudaGetSymbolAddress(&fbb_, g_fb);
    cudaGetSymbolAddress(&phi_, g_phi); cudaGetSymbolAddress(&plo_, g_plo);
    cudaGetSymbolAddress(&fhi_, g_fhi); cudaGetSymbolAddress(&flo_, g_flo);
    cudaGetSymbolAddress(&chi_, g_chi); cudaGetSymbolAddress(&clo_, g_clo);
    cudaGetSymbolAddress(&whi_, g_whi); cudaGetSymbolAddress(&wlo_, g_wlo);
    float* hb = (float*)hb_; float* qb = (float*)qb_;
    float* kb = (float*)kb_; float* vb = (float*)vb_; float* fbb = (float*)fbb_;
    __nv_bfloat16* phi = (__nv_bfloat16*)phi_; __nv_bfloat16* plo = (__nv_bfloat16*)plo_;
    __nv_bfloat16* fhi = (__nv_bfloat16*)fhi_; __nv_bfloat16* flo = (__nv_bfloat16*)flo_;
    __nv_bfloat16* chi = (__nv_bfloat16*)chi_; __nv_bfloat16* clo = (__nv_bfloat16*)clo_;
    __nv_bfloat16* whi = (__nv_bfloat16*)whi_; __nv_bfloat16* wlo = (__nv_bfloat16*)wlo_;

    cudaFuncSetAttribute(k_attn, cudaFuncAttributeMaxDynamicSharedMemorySize, AT_SMEM);
    cudaFuncSetAttribute(k_gemm, cudaFuncAttributeMaxDynamicSharedMemorySize, GSMEM);

    const int NDv4 = NN*DD/4;

    // edges -> CSR
    k_detect  <<<1, 32>>>((const int*)eidx);
    k_convert <<<EE/256, 256>>>(eidx);
    k_deg_init<<<NN/256, 256>>>();
    k_deg_edges<<<EE/256, 256>>>();
    k_dinv    <<<NN/256, 256>>>();
    k_scan    <<<1, 512>>>();
    k_place   <<<EE/256, 256>>>();

    // weight transpose + split
    auto wt = [&](const float* W, unsigned off, int K_, int N_) {
        k_wt<<<dim3(N_/32, K_/32), 256>>>(W, whi + off, wlo + off, K_, N_);
    };
    wt(gcn_in_w,  W_GCNIN,  512, 512);
    wt(gcn_out_w, W_GCNOUT, 512, 512);
    for (int i = 0; i < LL; i++) {
        wt(Wq + (size_t)i*262144, W_Q(i),  512, 512);
        wt(Wk + (size_t)i*262144, W_Kk(i), 512, 512);
        wt(Wv + (size_t)i*262144, W_Vv(i), 512, 512);
        wt(Wo + (size_t)i*262144, W_Oo(i), 512, 512);
        wt(geglu_w + (size_t)i*2097152, W_GEGLU(i), 512, 4096);
        wt(ffo_w   + (size_t)i*1048576, W_FFO(i),  2048, 512);
    }
    // cond split (reused by all layers)
    k_asplit<<<(NKV*DD/4)/256, 256>>>(cond, chi, clo, NKV*DD/4);

    // BatchNorm -> phi/plo
    k_bnstat_zero<<<1, 512>>>();
    k_bn_partial <<<64, 512>>>(x);
    k_bn_final   <<<1, 512>>>();
    k_bn_apply   <<<NDv4/256, 256>>>(x, bn_w, bn_b);

    // GCN in: qb = bn @ W; h = gather(qb) + self + bias
    gemm(phi, plo, whi + W_GCNIN, wlo + W_GCNIN, qb, nullptr, nullptr, nullptr, nullptr,
         NN, 512, 512, 512, 0);
    k_gather<<<NN, 128>>>(qb, hb, gcn_in_b, nullptr);

    for (int i = 0; i < LL; i++) {
        // attention block
        k_ln<<<NN/8, 256>>>(hb, ln2_w + i*DD, ln2_b + i*DD);
        gemm(phi, plo, whi + W_Q(i),  wlo + W_Q(i),  qb, nullptr, nullptr, nullptr, nullptr,
             NN,  512, 512, 512, 0);
        gemm(chi, clo, whi + W_Kk(i), wlo + W_Kk(i), kb, nullptr, nullptr, nullptr, nullptr,
             NKV, 512, 512, 512, 0);
        gemm(chi, clo, whi + W_Vv(i), wlo + W_Vv(i), vb, nullptr, nullptr, nullptr, nullptr,
             NKV, 512, 512, 512, 0);
        k_attn<<<dim3(BSb*HH, 16), 256, AT_SMEM>>>();
        gemm(phi, plo, whi + W_Oo(i), wlo + W_Oo(i), hb, nullptr, hb, nullptr, nullptr,
             NN, 512, 512, 512, 0);                                // h += o @ Wo
        // feed-forward (GEGLU)
        k_ln<<<NN/8, 256>>>(hb, ln3_w + i*DD, ln3_b + i*DD);
        gemm(phi, plo, whi + W_GEGLU(i), wlo + W_GEGLU(i), fbb,
             geglu_b + (size_t)i*4096, nullptr, nullptr, nullptr,
             NN, 2048, 512, 2048, 0);                              // val
        gemm(phi, plo, whi + W_GEGLU(i) + 2048u*512u, wlo + W_GEGLU(i) + 2048u*512u, fbb,
             geglu_b + (size_t)i*4096 + 2048, nullptr, fhi, flo,
             NN, 2048, 512, 2048, 1);                              // f = val*gelu(gate) -> bf16
        gemm(fhi, flo, whi + W_FFO(i), wlo + W_FFO(i), hb,
             ffo_b + (size_t)i*DD, hb, nullptr, nullptr,
             NN, 512, 2048, 512, 0);                               // h += f @ W + b
    }

    // GCN out + residual input: qb = h @ W; out = gather(qb) + self + bias + x
    k_asplit<<<NDv4/256, 256>>>(hb, phi, plo, NDv4);
    gemm(phi, plo, whi + W_GCNOUT, wlo + W_GCNOUT, qb, nullptr, nullptr, nullptr, nullptr,
         NN, 512, 512, 512, 0);
    k_gather<<<NN, 128>>>(qb, (float*)d_out, gcn_out_b, x);
}